// round 1
// baseline (speedup 1.0000x reference)
#include <cuda_runtime.h>

#define B   4096
#define DL  128
#define DT  768

typedef unsigned long long ull;

// ---------------- device scratch (no allocations allowed) ----------------
__device__ float g_ln[B * DL];     // normalized logits
__device__ float g_tn[B * DT];     // normalized teacher
__device__ float g_denom[B];       // per-row sum exp(sim) (diag excluded)
__device__ float g_possum[B];      // per-row sum sim*mask
__device__ float g_cnt[B];         // per-row mask count
__device__ float g_scal[2];        // [0]=distill sum, [1]=quant sum

// ---------------- packed f32x2 helpers (full-rate FP32 on sm_103a) -------
__device__ __forceinline__ ull pack2(float lo, float hi) {
    ull r;
    asm("mov.b64 %0, {%1, %2};" : "=l"(r) : "f"(lo), "f"(hi));
    return r;
}
__device__ __forceinline__ float2 unpack2(ull v) {
    float2 r;
    asm("mov.b64 {%0, %1}, %2;" : "=f"(r.x), "=f"(r.y) : "l"(v));
    return r;
}
#define FMA2(d, a, b) asm("fma.rn.f32x2 %0, %1, %2, %0;" : "+l"(d) : "l"(a), "l"(b))

// ---------------- kernel 0: zero accumulators ----------------------------
__global__ void zero_kernel() {
    int i = blockIdx.x * blockDim.x + threadIdx.x;
    if (i < B) { g_denom[i] = 0.f; g_possum[i] = 0.f; g_cnt[i] = 0.f; }
    if (i < 2) g_scal[i] = 0.f;
}

// ---------------- kernel 1: normalize logits + quant loss ----------------
__global__ void norm_logits_kernel(const float* __restrict__ logits) {
    int row = blockIdx.x, tid = threadIdx.x;
    int lane = tid & 31, wid = tid >> 5;
    float x = logits[row * DL + tid];
    float ss = x * x;
    #pragma unroll
    for (int o = 16; o; o >>= 1) ss += __shfl_xor_sync(0xffffffffu, ss, o);
    __shared__ float sh[4];
    if (!lane) sh[wid] = ss;
    __syncthreads();
    float tot = sh[0] + sh[1] + sh[2] + sh[3];
    float inv = 1.0f / fmaxf(sqrtf(tot), 1e-12f);
    g_ln[row * DL + tid] = x * inv;

    // quantization term: | |x| - 1 |
    float q = fabsf(fabsf(x) - 1.0f);
    #pragma unroll
    for (int o = 16; o; o >>= 1) q += __shfl_xor_sync(0xffffffffu, q, o);
    __syncthreads();
    if (!lane) sh[wid] = q;
    __syncthreads();
    if (!tid) atomicAdd(&g_scal[1], sh[0] + sh[1] + sh[2] + sh[3]);
}

// ---------------- kernel 2: normalize teacher ----------------------------
__global__ void norm_teacher_kernel(const float* __restrict__ t) {
    int row = blockIdx.x, tid = threadIdx.x;
    int lane = tid & 31, wid = tid >> 5;
    const float* p = t + (size_t)row * DT;
    float x0 = p[tid], x1 = p[tid + 256], x2 = p[tid + 512];
    float ss = x0 * x0 + x1 * x1 + x2 * x2;
    #pragma unroll
    for (int o = 16; o; o >>= 1) ss += __shfl_xor_sync(0xffffffffu, ss, o);
    __shared__ float sh[8];
    if (!lane) sh[wid] = ss;
    __syncthreads();
    float tot = 0.f;
    #pragma unroll
    for (int w = 0; w < 8; w++) tot += sh[w];
    float inv = 1.0f / fmaxf(sqrtf(tot), 1e-12f);
    float* o = g_tn + (size_t)row * DT;
    o[tid] = x0 * inv; o[tid + 256] = x1 * inv; o[tid + 512] = x2 * inv;
}

// ---------------- tile GEMM helper: acc += Xi @ Xj^T over ktot -----------
__device__ __forceinline__ void gemm_tile(
    const float* __restrict__ srcA, const float* __restrict__ srcB,
    int ld, int ktot, ull acc[8][4],
    float (&As)[16][128], float (&Bs)[16][128],
    int tid, int tx, int ty)
{
    int lrow = tid >> 1;
    int lkh  = (tid & 1) * 8;
    for (int k0 = 0; k0 < ktot; k0 += 16) {
        __syncthreads();
        const float* pa = srcA + (size_t)lrow * ld + k0 + lkh;
        const float* pb = srcB + (size_t)lrow * ld + k0 + lkh;
        float4 a0 = *(const float4*)pa, a1 = *(const float4*)(pa + 4);
        float4 b0 = *(const float4*)pb, b1 = *(const float4*)(pb + 4);
        As[lkh + 0][lrow] = a0.x; As[lkh + 1][lrow] = a0.y;
        As[lkh + 2][lrow] = a0.z; As[lkh + 3][lrow] = a0.w;
        As[lkh + 4][lrow] = a1.x; As[lkh + 5][lrow] = a1.y;
        As[lkh + 6][lrow] = a1.z; As[lkh + 7][lrow] = a1.w;
        Bs[lkh + 0][lrow] = b0.x; Bs[lkh + 1][lrow] = b0.y;
        Bs[lkh + 2][lrow] = b0.z; Bs[lkh + 3][lrow] = b0.w;
        Bs[lkh + 4][lrow] = b1.x; Bs[lkh + 5][lrow] = b1.y;
        Bs[lkh + 6][lrow] = b1.z; Bs[lkh + 7][lrow] = b1.w;
        __syncthreads();
        #pragma unroll
        for (int k = 0; k < 16; k++) {
            float4 af0 = *(const float4*)&As[k][ty * 8];
            float4 af1 = *(const float4*)&As[k][ty * 8 + 4];
            float4 bf0 = *(const float4*)&Bs[k][tx * 8];
            float4 bf1 = *(const float4*)&Bs[k][tx * 8 + 4];
            ull b2_0 = pack2(bf0.x, bf0.y);
            ull b2_1 = pack2(bf0.z, bf0.w);
            ull b2_2 = pack2(bf1.x, bf1.y);
            ull b2_3 = pack2(bf1.z, bf1.w);
            float am[8] = {af0.x, af0.y, af0.z, af0.w, af1.x, af1.y, af1.z, af1.w};
            #pragma unroll
            for (int m = 0; m < 8; m++) {
                ull a2 = pack2(am[m], am[m]);
                FMA2(acc[m][0], a2, b2_0);
                FMA2(acc[m][1], a2, b2_1);
                FMA2(acc[m][2], a2, b2_2);
                FMA2(acc[m][3], a2, b2_3);
            }
        }
    }
}

// ---------------- kernel 3: fused pairwise tile kernel -------------------
__global__ void __launch_bounds__(256) pair_kernel(
    const float* __restrict__ hash, const int* __restrict__ mask)
{
    __shared__ float As[16][128];
    __shared__ float Bs[16][128];
    __shared__ float dsh[8];

    int tid = threadIdx.x;
    int tx = tid & 15, ty = tid >> 4;
    int i0 = blockIdx.y * 128, j0 = blockIdx.x * 128;

    ull accT[8][4];
    ull accS[8][4];
    #pragma unroll
    for (int m = 0; m < 8; m++)
        #pragma unroll
        for (int n = 0; n < 4; n++) accT[m][n] = 0ull;

    // teacher Gram tile (K=768)
    gemm_tile(g_tn + (size_t)i0 * DT, g_tn + (size_t)j0 * DT, DT, DT,
              accT, As, Bs, tid, tx, ty);

    // hash Gram tile (K=128)
    #pragma unroll
    for (int m = 0; m < 8; m++)
        #pragma unroll
        for (int n = 0; n < 4; n++) accS[m][n] = 0ull;
    gemm_tile(hash + (size_t)i0 * DL, hash + (size_t)j0 * DL, DL, DL,
              accS, As, Bs, tid, tx, ty);

    // distill partial: sum (h/128 - t)^2
    float distill = 0.f;
    #pragma unroll
    for (int m = 0; m < 8; m++) {
        #pragma unroll
        for (int n2 = 0; n2 < 4; n2++) {
            float2 t = unpack2(accT[m][n2]);
            float2 h = unpack2(accS[m][n2]);
            float d0 = h.x * (1.0f / 128.0f) - t.x;
            float d1 = h.y * (1.0f / 128.0f) - t.y;
            distill += d0 * d0 + d1 * d1;
        }
    }

    // ln Gram tile (K=128) into accS (accT dead now)
    #pragma unroll
    for (int m = 0; m < 8; m++)
        #pragma unroll
        for (int n = 0; n < 4; n++) accS[m][n] = 0ull;
    gemm_tile(g_ln + (size_t)i0 * DL, g_ln + (size_t)j0 * DL, DL, DL,
              accS, As, Bs, tid, tx, ty);

    // contrastive epilogue
    float denomL[8], posL[8], cntL[8];
    #pragma unroll
    for (int m = 0; m < 8; m++) { denomL[m] = 0.f; posL[m] = 0.f; cntL[m] = 0.f; }

    #pragma unroll
    for (int m = 0; m < 8; m++) {
        int gi = i0 + ty * 8 + m;
        const int* mrow = mask + (size_t)gi * B + j0 + tx * 8;
        int4 mv0 = *(const int4*)mrow;
        int4 mv1 = *(const int4*)(mrow + 4);
        int mv[8] = {mv0.x, mv0.y, mv0.z, mv0.w, mv1.x, mv1.y, mv1.z, mv1.w};
        float s[8];
        #pragma unroll
        for (int n2 = 0; n2 < 4; n2++) {
            float2 v = unpack2(accS[m][n2]);
            s[2 * n2]     = v.x * 5.0f;   // / TEMPERATURE
            s[2 * n2 + 1] = v.y * 5.0f;
        }
        #pragma unroll
        for (int n = 0; n < 8; n++) {
            int gj = j0 + tx * 8 + n;
            if (gi != gj) denomL[m] += __expf(s[n]);
            if (mv[n]) { posL[m] += s[n]; cntL[m] += 1.0f; }
        }
    }

    // reduce across the 16 tx lanes (stays within half-warp: offsets < 16)
    #pragma unroll
    for (int m = 0; m < 8; m++) {
        #pragma unroll
        for (int o = 1; o < 16; o <<= 1) {
            denomL[m] += __shfl_xor_sync(0xffffffffu, denomL[m], o);
            posL[m]   += __shfl_xor_sync(0xffffffffu, posL[m], o);
            cntL[m]   += __shfl_xor_sync(0xffffffffu, cntL[m], o);
        }
    }
    if (tx == 0) {
        #pragma unroll
        for (int m = 0; m < 8; m++) {
            int gi = i0 + ty * 8 + m;
            atomicAdd(&g_denom[gi], denomL[m]);
            atomicAdd(&g_possum[gi], posL[m]);
            atomicAdd(&g_cnt[gi], cntL[m]);
        }
    }

    // distill block reduction -> one atomic per CTA
    #pragma unroll
    for (int o = 16; o; o >>= 1) distill += __shfl_xor_sync(0xffffffffu, distill, o);
    int lane = tid & 31, wid = tid >> 5;
    if (!lane) dsh[wid] = distill;
    __syncthreads();
    if (!tid) {
        float s = 0.f;
        #pragma unroll
        for (int w = 0; w < 8; w++) s += dsh[w];
        atomicAdd(&g_scal[0], s);
    }
}

// ---------------- kernel 4: finalize scalar ------------------------------
__global__ void finalize_kernel(float* __restrict__ out) {
    int tid = threadIdx.x;
    float local = 0.f, np = 0.f;
    for (int r = tid; r < B; r += 256) {
        float c = g_cnt[r];
        if (c > 0.f) {
            local += logf(g_denom[r]) - g_possum[r] / c;
            np += 1.f;
        }
    }
    __shared__ float sred[256];
    __shared__ float snp[256];
    sred[tid] = local; snp[tid] = np;
    __syncthreads();
    for (int s = 128; s; s >>= 1) {
        if (tid < s) { sred[tid] += sred[tid + s]; snp[tid] += snp[tid + s]; }
        __syncthreads();
    }
    if (!tid) {
        float cont    = sred[0] / fmaxf(snp[0], 1.0f);
        float distill = g_scal[0] / ((float)B * (float)B);
        float quant   = g_scal[1] / ((float)B * (float)DL);
        out[0] = cont + 0.5f * distill + 0.01f * quant;
    }
}

// ---------------- entry point --------------------------------------------
extern "C" void kernel_launch(void* const* d_in, const int* in_sizes, int n_in,
                              void* d_out, int out_size) {
    const float* logits  = (const float*)d_in[0];
    const float* hash    = (const float*)d_in[1];
    const float* teacher = (const float*)d_in[2];
    const int*   mask    = (const int*)d_in[3];   // bool as 4-byte (i32 or f32): nonzero test
    float* out = (float*)d_out;

    zero_kernel<<<(B + 255) / 256, 256>>>();
    norm_logits_kernel<<<B, 128>>>(logits);
    norm_teacher_kernel<<<B, 256>>>(teacher);
    pair_kernel<<<dim3(32, 32), 256>>>(hash, mask);
    finalize_kernel<<<1, 256>>>(out);
}

// round 3
// speedup vs baseline: 3.6361x; 3.6361x over previous
#include <cuda_runtime.h>

#define B   4096
#define DL  128
#define DT  768
#define NTILE 32                         // B / 128

#define C_TT_SZ  (768*768)
#define C_TH_SZ  (768*128)
#define C_HH_SZ  (128*128)
#define C_TH_OFF (C_TT_SZ)
#define C_HH_OFF (C_TT_SZ + C_TH_SZ)
#define C_TOTAL  (C_TT_SZ + C_TH_SZ + C_HH_SZ)   // 704512

#define MAXPAIRS (1 << 22)

typedef unsigned long long ull;

// ---------------- device scratch ----------------
__device__ float g_ln[B * DL];
__device__ float g_tn[B * DT];
__device__ float g_C[C_TOTAL];
__device__ float g_denom[B];
__device__ float g_possum[B];
__device__ float g_cnt[B];
__device__ float g_scal[8];   // [1]=quant, [2]=G_TT, [3]=G_TH, [4]=G_HH
__device__ int   g_pairs[MAXPAIRS];
__device__ int   g_npairs;

// ---------------- packed f32x2 helpers ----------------
__device__ __forceinline__ ull pack2(float lo, float hi) {
    ull r; asm("mov.b64 %0, {%1, %2};" : "=l"(r) : "f"(lo), "f"(hi)); return r;
}
__device__ __forceinline__ float2 unpack2(ull v) {
    float2 r; asm("mov.b64 {%0, %1}, %2;" : "=f"(r.x), "=f"(r.y) : "l"(v)); return r;
}
#define FMA2(d, a, b) asm("fma.rn.f32x2 %0, %1, %2, %0;" : "+l"(d) : "l"(a), "l"(b))

// shared inner product step: 16 k-slices from As/Bs into 8x8 acc
__device__ __forceinline__ void fma16(const float (&As)[16][128], const float (&Bs)[16][128],
                                      int tx, int ty, ull (&acc)[8][4]) {
    #pragma unroll
    for (int k = 0; k < 16; k++) {
        float4 af0 = *(const float4*)&As[k][ty * 8];
        float4 af1 = *(const float4*)&As[k][ty * 8 + 4];
        float4 bf0 = *(const float4*)&Bs[k][tx * 8];
        float4 bf1 = *(const float4*)&Bs[k][tx * 8 + 4];
        ull b0 = pack2(bf0.x, bf0.y), b1 = pack2(bf0.z, bf0.w);
        ull b2 = pack2(bf1.x, bf1.y), b3 = pack2(bf1.z, bf1.w);
        float am[8] = {af0.x, af0.y, af0.z, af0.w, af1.x, af1.y, af1.z, af1.w};
        #pragma unroll
        for (int m = 0; m < 8; m++) {
            ull a2 = pack2(am[m], am[m]);
            FMA2(acc[m][0], a2, b0);
            FMA2(acc[m][1], a2, b1);
            FMA2(acc[m][2], a2, b2);
            FMA2(acc[m][3], a2, b3);
        }
    }
}

// ---------------- kernel: zero ----------------
__global__ void zero_kernel() {
    int i = blockIdx.x * blockDim.x + threadIdx.x;
    if (i < C_TOTAL) g_C[i] = 0.f;
    if (i < B) { g_denom[i] = 0.f; g_possum[i] = 0.f; g_cnt[i] = 0.f; }
    if (i < 8) g_scal[i] = 0.f;
    if (i == 0) g_npairs = 0;
}

// ---------------- kernel: normalize logits + quant ----------------
__global__ void norm_logits_kernel(const float* __restrict__ logits) {
    int row = blockIdx.x, tid = threadIdx.x;
    int lane = tid & 31, wid = tid >> 5;
    float x = logits[row * DL + tid];
    float ss = x * x;
    #pragma unroll
    for (int o = 16; o; o >>= 1) ss += __shfl_xor_sync(0xffffffffu, ss, o);
    __shared__ float sh[4];
    if (!lane) sh[wid] = ss;
    __syncthreads();
    float tot = sh[0] + sh[1] + sh[2] + sh[3];
    float inv = 1.0f / fmaxf(sqrtf(tot), 1e-12f);
    g_ln[row * DL + tid] = x * inv;

    float q = fabsf(fabsf(x) - 1.0f);
    #pragma unroll
    for (int o = 16; o; o >>= 1) q += __shfl_xor_sync(0xffffffffu, q, o);
    __syncthreads();
    if (!lane) sh[wid] = q;
    __syncthreads();
    if (!tid) atomicAdd(&g_scal[1], sh[0] + sh[1] + sh[2] + sh[3]);
}

// ---------------- kernel: normalize teacher ----------------
__global__ void norm_teacher_kernel(const float* __restrict__ t) {
    int row = blockIdx.x, tid = threadIdx.x;
    int lane = tid & 31, wid = tid >> 5;
    const float* p = t + (size_t)row * DT;
    float x0 = p[tid], x1 = p[tid + 256], x2 = p[tid + 512];
    float ss = x0 * x0 + x1 * x1 + x2 * x2;
    #pragma unroll
    for (int o = 16; o; o >>= 1) ss += __shfl_xor_sync(0xffffffffu, ss, o);
    __shared__ float sh[8];
    if (!lane) sh[wid] = ss;
    __syncthreads();
    float tot = 0.f;
    #pragma unroll
    for (int w = 0; w < 8; w++) tot += sh[w];
    float inv = 1.0f / fmaxf(sqrtf(tot), 1e-12f);
    float* o = g_tn + (size_t)row * DT;
    o[tid] = x0 * inv; o[tid + 256] = x1 * inv; o[tid + 512] = x2 * inv;
}

// ---------------- kernel: extract sparse positives ----------------
__global__ void extract_kernel(const int* __restrict__ mask) {
    int t = blockIdx.x * blockDim.x + threadIdx.x;
    int base = t * 16;
    int loc[16]; int nf = 0;
    #pragma unroll
    for (int u = 0; u < 16; u += 4) {
        int4 v = *(const int4*)(mask + base + u);
        if (v.x) loc[nf++] = base + u;
        if (v.y) loc[nf++] = base + u + 1;
        if (v.z) loc[nf++] = base + u + 2;
        if (v.w) loc[nf++] = base + u + 3;
    }
    int lane = threadIdx.x & 31;
    int pre = nf;
    #pragma unroll
    for (int o = 1; o < 32; o <<= 1) {
        int x = __shfl_up_sync(0xffffffffu, pre, o);
        if (lane >= o) pre += x;
    }
    int tot = __shfl_sync(0xffffffffu, pre, 31);
    int basep = 0;
    if (lane == 31 && tot) basep = atomicAdd(&g_npairs, tot);
    basep = __shfl_sync(0xffffffffu, basep, 31);
    int off = basep + pre - nf;
    for (int u = 0; u < nf; u++)
        if (off + u < MAXPAIRS) g_pairs[off + u] = loc[u];
}

// ---------------- kernel: positive-pair dots -> possum/cnt ----------------
__global__ void pos_kernel() {
    int n = g_npairs; if (n > MAXPAIRS) n = MAXPAIRS;
    int gw = (blockIdx.x * blockDim.x + threadIdx.x) >> 5;
    int lane = threadIdx.x & 31;
    int nw = (gridDim.x * blockDim.x) >> 5;
    for (int p = gw; p < n; p += nw) {
        int code = g_pairs[p];
        int i = code >> 12, j = code & 4095;
        float4 x = ((const float4*)(g_ln + (size_t)i * DL))[lane];
        float4 y = ((const float4*)(g_ln + (size_t)j * DL))[lane];
        float s = x.x * y.x + x.y * y.y + x.z * y.z + x.w * y.w;
        #pragma unroll
        for (int o = 16; o; o >>= 1) s += __shfl_xor_sync(0xffffffffu, s, o);
        if (!lane) {
            atomicAdd(&g_possum[i], s * 5.0f);
            atomicAdd(&g_cnt[i], 1.0f);
        }
    }
}

// ---------------- kernel: small Grams (TT triangle, TH, HH), split-K ------
__global__ void __launch_bounds__(256, 2) gram_kernel(const float* __restrict__ hash) {
    __shared__ float As[16][128];
    __shared__ float Bs[16][128];
    int tid = threadIdx.x, tx = tid & 15, ty = tid >> 4;
    int jid = blockIdx.x;

    const float *A, *Bm; int lda, ldb, u0, v0, kbase, ldC; float* Cp;
    if (jid < 336) {                       // TT upper-triangle: 21 tiles x 16 k-chunks
        int t = jid >> 4, chunk = jid & 15;
        int tu = 0;
        while (t >= 6 - tu) { t -= 6 - tu; tu++; }
        int tv = tu + t;
        A = g_tn; Bm = g_tn; lda = DT; ldb = DT;
        u0 = tu * 128; v0 = tv * 128;
        Cp = g_C; ldC = DT; kbase = chunk * 256;
    } else if (jid < 432) {                // TH: 6 tiles x 16 k-chunks
        int t = (jid - 336) >> 4, chunk = (jid - 336) & 15;
        A = g_tn; Bm = hash; lda = DT; ldb = DL;
        u0 = t * 128; v0 = 0;
        Cp = g_C + C_TH_OFF; ldC = DL; kbase = chunk * 256;
    } else {                               // HH: 1 tile x 16 k-chunks
        int chunk = jid - 432;
        A = hash; Bm = hash; lda = DL; ldb = DL;
        u0 = 0; v0 = 0;
        Cp = g_C + C_HH_OFF; ldC = DL; kbase = chunk * 256;
    }

    ull acc[8][4];
    #pragma unroll
    for (int m = 0; m < 8; m++)
        #pragma unroll
        for (int nn = 0; nn < 4; nn++) acc[m][nn] = 0ull;

    int lr = tid >> 4, lc = (tid & 15) * 8;
    for (int k0 = 0; k0 < 256; k0 += 16) {
        __syncthreads();
        const float* pa = A  + (size_t)(kbase + k0 + lr) * lda + u0 + lc;
        const float* pb = Bm + (size_t)(kbase + k0 + lr) * ldb + v0 + lc;
        *(float4*)&As[lr][lc]     = *(const float4*)pa;
        *(float4*)&As[lr][lc + 4] = *(const float4*)(pa + 4);
        *(float4*)&Bs[lr][lc]     = *(const float4*)pb;
        *(float4*)&Bs[lr][lc + 4] = *(const float4*)(pb + 4);
        __syncthreads();
        fma16(As, Bs, tx, ty, acc);
    }

    #pragma unroll
    for (int m = 0; m < 8; m++) {
        float* crow = Cp + (size_t)(u0 + ty * 8 + m) * ldC + v0 + tx * 8;
        #pragma unroll
        for (int n2 = 0; n2 < 4; n2++) {
            float2 v = unpack2(acc[m][n2]);
            atomicAdd(&crow[2 * n2],     v.x);
            atomicAdd(&crow[2 * n2 + 1], v.y);
        }
    }
}

// ---------------- kernel: weighted squared-Frobenius reduction -----------
__global__ void square_kernel() {
    int i = blockIdx.x * blockDim.x + threadIdx.x;
    float vTT = 0.f, vTH = 0.f, vHH = 0.f;
    if (i < C_TT_SZ) {
        float c = g_C[i];
        int u = i / 768, v = i - u * 768;
        int tu = u >> 7, tv = v >> 7;
        float w = (tv > tu) ? 2.f : ((tv == tu) ? 1.f : 0.f);
        vTT = w * c * c;
    } else if (i < C_HH_OFF) {
        float c = g_C[i]; vTH = c * c;
    } else if (i < C_TOTAL) {
        float c = g_C[i]; vHH = c * c;
    }
    #pragma unroll
    for (int o = 16; o; o >>= 1) {
        vTT += __shfl_xor_sync(0xffffffffu, vTT, o);
        vTH += __shfl_xor_sync(0xffffffffu, vTH, o);
        vHH += __shfl_xor_sync(0xffffffffu, vHH, o);
    }
    __shared__ float sh[3][8];
    int lane = threadIdx.x & 31, wid = threadIdx.x >> 5;
    if (!lane) { sh[0][wid] = vTT; sh[1][wid] = vTH; sh[2][wid] = vHH; }
    __syncthreads();
    if (threadIdx.x < 3) {
        float s = 0.f;
        #pragma unroll
        for (int w = 0; w < 8; w++) s += sh[threadIdx.x][w];
        if (s != 0.f) atomicAdd(&g_scal[2 + threadIdx.x], s);
    }
}

// ---------------- kernel: symmetric ln-Gram -> denominators --------------
__global__ void __launch_bounds__(256, 2) pair_kernel() {
    __shared__ float As[16][128];
    __shared__ float Bs[16][128];
    __shared__ float cd[128];

    int tid = threadIdx.x, tx = tid & 15, ty = tid >> 4;

    // decode upper-triangle tile (bi <= bj) from linear blockIdx.x in [0,528)
    int t = blockIdx.x, bi = 0;
    while (t >= NTILE - bi) { t -= NTILE - bi; bi++; }
    int bj = bi + t;
    int i0 = bi * 128, j0 = bj * 128;
    bool diag = (bi == bj);

    ull acc[8][4];
    #pragma unroll
    for (int m = 0; m < 8; m++)
        #pragma unroll
        for (int nn = 0; nn < 4; nn++) acc[m][nn] = 0ull;

    const float* Abase = g_ln + (size_t)i0 * DL;
    const float* Bbase = g_ln + (size_t)j0 * DL;
    int lrow = tid >> 1, lkh = (tid & 1) * 8;
    for (int k0 = 0; k0 < DL; k0 += 16) {
        __syncthreads();
        const float* pa = Abase + (size_t)lrow * DL + k0 + lkh;
        const float* pb = Bbase + (size_t)lrow * DL + k0 + lkh;
        float4 a0 = *(const float4*)pa, a1 = *(const float4*)(pa + 4);
        float4 b0 = *(const float4*)pb, b1 = *(const float4*)(pb + 4);
        As[lkh + 0][lrow] = a0.x; As[lkh + 1][lrow] = a0.y;
        As[lkh + 2][lrow] = a0.z; As[lkh + 3][lrow] = a0.w;
        As[lkh + 4][lrow] = a1.x; As[lkh + 5][lrow] = a1.y;
        As[lkh + 6][lrow] = a1.z; As[lkh + 7][lrow] = a1.w;
        Bs[lkh + 0][lrow] = b0.x; Bs[lkh + 1][lrow] = b0.y;
        Bs[lkh + 2][lrow] = b0.z; Bs[lkh + 3][lrow] = b0.w;
        Bs[lkh + 4][lrow] = b1.x; Bs[lkh + 5][lrow] = b1.y;
        Bs[lkh + 6][lrow] = b1.z; Bs[lkh + 7][lrow] = b1.w;
        __syncthreads();
        fma16(As, Bs, tx, ty, acc);
    }

    // epilogue: e = exp(5*sim); row sums always, col sums only off-diagonal
    float colD[8];
    #pragma unroll
    for (int n = 0; n < 8; n++) colD[n] = 0.f;

    #pragma unroll
    for (int m = 0; m < 8; m++) {
        int gi = i0 + ty * 8 + m;
        float rowD = 0.f;
        #pragma unroll
        for (int n2 = 0; n2 < 4; n2++) {
            float2 v = unpack2(acc[m][n2]);
            float e0 = __expf(v.x * 5.0f);
            float e1 = __expf(v.y * 5.0f);
            int gj0 = j0 + tx * 8 + 2 * n2;
            if (gi == gj0)     e0 = 0.f;   // exclude diagonal from denom
            if (gi == gj0 + 1) e1 = 0.f;
            rowD += e0 + e1;
            colD[2 * n2]     += e0;
            colD[2 * n2 + 1] += e1;
        }
        #pragma unroll
        for (int o = 1; o < 16; o <<= 1)
            rowD += __shfl_xor_sync(0xffffffffu, rowD, o);
        if (tx == 0) atomicAdd(&g_denom[gi], rowD);
    }

    if (!diag) {
        if (tid < 128) cd[tid] = 0.f;
        __syncthreads();
        #pragma unroll
        for (int n = 0; n < 8; n++) atomicAdd(&cd[tx * 8 + n], colD[n]);
        __syncthreads();
        if (tid < 128) atomicAdd(&g_denom[j0 + tid], cd[tid]);
    }
}

// ---------------- kernel: finalize ----------------
__global__ void finalize_kernel(float* __restrict__ out) {
    int tid = threadIdx.x;
    float local = 0.f, np = 0.f;
    for (int r = tid; r < B; r += 256) {
        float c = g_cnt[r];
        if (c > 0.f) {
            local += logf(g_denom[r]) - g_possum[r] / c;
            np += 1.f;
        }
    }
    __shared__ float sred[256];
    __shared__ float snp[256];
    sred[tid] = local; snp[tid] = np;
    __syncthreads();
    for (int s = 128; s; s >>= 1) {
        if (tid < s) { sred[tid] += sred[tid + s]; snp[tid] += snp[tid + s]; }
        __syncthreads();
    }
    if (!tid) {
        float cont = sred[0] / fmaxf(snp[0], 1.0f);
        float distill_sum = g_scal[4] * (1.0f / 16384.0f)
                          - g_scal[3] * (1.0f / 64.0f)
                          + g_scal[2];
        float distill = distill_sum / ((float)B * (float)B);
        float quant = g_scal[1] / ((float)B * (float)DL);
        out[0] = cont + 0.5f * distill + 0.01f * quant;
    }
}

// ---------------- entry point ----------------
extern "C" void kernel_launch(void* const* d_in, const int* in_sizes, int n_in,
                              void* d_out, int out_size) {
    const float* logits  = (const float*)d_in[0];
    const float* hash    = (const float*)d_in[1];
    const float* teacher = (const float*)d_in[2];
    const int*   mask    = (const int*)d_in[3];   // bool stored 4-byte; nonzero test
    float* out = (float*)d_out;

    zero_kernel<<<(C_TOTAL + 255) / 256, 256>>>();
    norm_logits_kernel<<<B, 128>>>(logits);
    norm_teacher_kernel<<<B, 256>>>(teacher);
    extract_kernel<<<4096, 256>>>(mask);
    pos_kernel<<<512, 256>>>();
    gram_kernel<<<448, 256>>>(hash);
    square_kernel<<<(C_TOTAL + 255) / 256, 256>>>();
    pair_kernel<<<528, 256>>>();
    finalize_kernel<<<1, 256>>>(out);
}

// round 4
// speedup vs baseline: 4.0035x; 1.1010x over previous
#include <cuda_runtime.h>

#define B   4096
#define DL  128
#define DT  768
#define NTILE 32                         // B / 128

#define C_TT_SZ  (768*768)
#define C_TH_SZ  (768*128)
#define C_HH_SZ  (128*128)
#define C_TH_OFF (C_TT_SZ)
#define C_HH_OFF (C_TT_SZ + C_TH_SZ)
#define C_TOTAL  (C_TT_SZ + C_TH_SZ + C_HH_SZ)   // 704512

#define MAXPAIRS (1 << 22)

// mega-kernel role partition
#define NB_TT   168      // 21 upper-tri tiles x 8 k-chunks
#define NB_TH   48       // 6 tiles x 8 k-chunks
#define NB_HH   8        // 1 tile x 8 k-chunks
#define NB_GRAM (NB_TT + NB_TH + NB_HH)          // 224
#define NB_PAIR 528
#define NB_POS  64

typedef unsigned long long ull;

// ---------------- device scratch ----------------
__device__ float g_ln[B * DL];
__device__ float g_tn[B * DT];
__device__ float g_C[C_TOTAL];
__device__ float g_denom[B];
__device__ float g_possum[B];
__device__ float g_cnt[B];
__device__ float g_scal[8];   // [1]=quant, [2]=G_TT, [3]=G_TH, [4]=G_HH
__device__ int   g_pairs[MAXPAIRS];
__device__ int   g_npairs;

// ---------------- packed f32x2 helpers ----------------
__device__ __forceinline__ ull pack2(float lo, float hi) {
    ull r; asm("mov.b64 %0, {%1, %2};" : "=l"(r) : "f"(lo), "f"(hi)); return r;
}
__device__ __forceinline__ float2 unpack2(ull v) {
    float2 r; asm("mov.b64 {%0, %1}, %2;" : "=f"(r.x), "=f"(r.y) : "l"(v)); return r;
}
#define FMA2(d, a, b) asm("fma.rn.f32x2 %0, %1, %2, %0;" : "+l"(d) : "l"(a), "l"(b))

// 16 k-slices from As/Bs into 8x8 acc (as 8x4 f32x2)
__device__ __forceinline__ void fma16(const float (&As)[16][128], const float (&Bs)[16][128],
                                      int tx, int ty, ull (&acc)[8][4]) {
    #pragma unroll
    for (int k = 0; k < 16; k++) {
        float4 af0 = *(const float4*)&As[k][ty * 8];
        float4 af1 = *(const float4*)&As[k][ty * 8 + 4];
        float4 bf0 = *(const float4*)&Bs[k][tx * 8];
        float4 bf1 = *(const float4*)&Bs[k][tx * 8 + 4];
        ull b0 = pack2(bf0.x, bf0.y), b1 = pack2(bf0.z, bf0.w);
        ull b2 = pack2(bf1.x, bf1.y), b3 = pack2(bf1.z, bf1.w);
        float am[8] = {af0.x, af0.y, af0.z, af0.w, af1.x, af1.y, af1.z, af1.w};
        #pragma unroll
        for (int m = 0; m < 8; m++) {
            ull a2 = pack2(am[m], am[m]);
            FMA2(acc[m][0], a2, b0);
            FMA2(acc[m][1], a2, b1);
            FMA2(acc[m][2], a2, b2);
            FMA2(acc[m][3], a2, b3);
        }
    }
}

// ---------------- kernel: zero ----------------
__global__ void zero_kernel() {
    int i = blockIdx.x * blockDim.x + threadIdx.x;
    if (i < C_TOTAL) g_C[i] = 0.f;
    if (i < B) { g_denom[i] = 0.f; g_possum[i] = 0.f; g_cnt[i] = 0.f; }
    if (i < 8) g_scal[i] = 0.f;
    if (i == 0) g_npairs = 0;
}

// ---------------- kernel: normalize logits + quant ----------------
__global__ void norm_logits_kernel(const float* __restrict__ logits) {
    int row = blockIdx.x, tid = threadIdx.x;
    int lane = tid & 31, wid = tid >> 5;
    float x = logits[row * DL + tid];
    float ss = x * x;
    #pragma unroll
    for (int o = 16; o; o >>= 1) ss += __shfl_xor_sync(0xffffffffu, ss, o);
    __shared__ float sh[4];
    if (!lane) sh[wid] = ss;
    __syncthreads();
    float tot = sh[0] + sh[1] + sh[2] + sh[3];
    float inv = 1.0f / fmaxf(sqrtf(tot), 1e-12f);
    g_ln[row * DL + tid] = x * inv;

    float q = fabsf(fabsf(x) - 1.0f);
    #pragma unroll
    for (int o = 16; o; o >>= 1) q += __shfl_xor_sync(0xffffffffu, q, o);
    __syncthreads();
    if (!lane) sh[wid] = q;
    __syncthreads();
    if (!tid) atomicAdd(&g_scal[1], sh[0] + sh[1] + sh[2] + sh[3]);
}

// ---------------- kernel: normalize teacher ----------------
__global__ void norm_teacher_kernel(const float* __restrict__ t) {
    int row = blockIdx.x, tid = threadIdx.x;
    int lane = tid & 31, wid = tid >> 5;
    const float* p = t + (size_t)row * DT;
    float x0 = p[tid], x1 = p[tid + 256], x2 = p[tid + 512];
    float ss = x0 * x0 + x1 * x1 + x2 * x2;
    #pragma unroll
    for (int o = 16; o; o >>= 1) ss += __shfl_xor_sync(0xffffffffu, ss, o);
    __shared__ float sh[8];
    if (!lane) sh[wid] = ss;
    __syncthreads();
    float tot = 0.f;
    #pragma unroll
    for (int w = 0; w < 8; w++) tot += sh[w];
    float inv = 1.0f / fmaxf(sqrtf(tot), 1e-12f);
    float* o = g_tn + (size_t)row * DT;
    o[tid] = x0 * inv; o[tid + 256] = x1 * inv; o[tid + 512] = x2 * inv;
}

// ---------------- kernel: sparse positive extraction (block-aggregated) --
__global__ void __launch_bounds__(256) extract_kernel(const int* __restrict__ mask) {
    int t = blockIdx.x * blockDim.x + threadIdx.x;
    int base = t * 32;
    int4 v[8];
    #pragma unroll
    for (int u = 0; u < 8; u++)
        v[u] = *(const int4*)(mask + base + u * 4);
    int nf = 0;
    #pragma unroll
    for (int u = 0; u < 8; u++)
        nf += (v[u].x != 0) + (v[u].y != 0) + (v[u].z != 0) + (v[u].w != 0);

    int lane = threadIdx.x & 31, wid = threadIdx.x >> 5;
    int pre = nf;
    #pragma unroll
    for (int o = 1; o < 32; o <<= 1) {
        int x = __shfl_up_sync(0xffffffffu, pre, o);
        if (lane >= o) pre += x;
    }
    __shared__ int wtot[8];
    __shared__ int bbase;
    if (lane == 31) wtot[wid] = pre;
    __syncthreads();
    if (threadIdx.x == 0) {
        int s = 0;
        #pragma unroll
        for (int w = 0; w < 8; w++) { int tmp = wtot[w]; wtot[w] = s; s += tmp; }
        bbase = s ? atomicAdd(&g_npairs, s) : 0;
    }
    __syncthreads();
    int off = bbase + wtot[wid] + pre - nf;
    #pragma unroll
    for (int u = 0; u < 8; u++) {
        int idx = base + u * 4;
        if (v[u].x && off < MAXPAIRS) g_pairs[off++] = idx;
        if (v[u].y && off < MAXPAIRS) g_pairs[off++] = idx + 1;
        if (v[u].z && off < MAXPAIRS) g_pairs[off++] = idx + 2;
        if (v[u].w && off < MAXPAIRS) g_pairs[off++] = idx + 3;
    }
}

// ======================= mega kernel roles =======================

// ---- gram role: split-K tall-skinny Grams, double-buffered ----
__device__ __forceinline__ void gram_role(
    int jid, const float* __restrict__ hash,
    float (&As)[2][16][128], float (&Bs)[2][16][128],
    int tid, int tx, int ty)
{
    const float *A, *Bm; int lda, ldb, u0, v0, kbase, ldC; float* Cp;
    if (jid < NB_TT) {                     // TT upper triangle of 6x6 tiles
        int t = jid >> 3, chunk = jid & 7;
        int tu = 0;
        while (t >= 6 - tu) { t -= 6 - tu; tu++; }
        int tv = tu + t;
        A = g_tn; Bm = g_tn; lda = DT; ldb = DT;
        u0 = tu * 128; v0 = tv * 128;
        Cp = g_C; ldC = DT; kbase = chunk * 512;
    } else if (jid < NB_TT + NB_TH) {      // TH
        int r = jid - NB_TT;
        int t = r >> 3, chunk = r & 7;
        A = g_tn; Bm = hash; lda = DT; ldb = DL;
        u0 = t * 128; v0 = 0;
        Cp = g_C + C_TH_OFF; ldC = DL; kbase = chunk * 512;
    } else {                               // HH
        int chunk = jid - NB_TT - NB_TH;
        A = hash; Bm = hash; lda = DL; ldb = DL;
        u0 = 0; v0 = 0;
        Cp = g_C + C_HH_OFF; ldC = DL; kbase = chunk * 512;
    }

    ull acc[8][4];
    #pragma unroll
    for (int m = 0; m < 8; m++)
        #pragma unroll
        for (int nn = 0; nn < 4; nn++) acc[m][nn] = 0ull;

    int lr = tid >> 4, lc = (tid & 15) * 8;
    const float* pa = A  + (size_t)(kbase + lr) * lda + u0 + lc;
    const float* pb = Bm + (size_t)(kbase + lr) * ldb + v0 + lc;

    // stage 0
    float4 a0 = *(const float4*)pa, a1 = *(const float4*)(pa + 4);
    float4 b0 = *(const float4*)pb, b1 = *(const float4*)(pb + 4);
    *(float4*)&As[0][lr][lc] = a0; *(float4*)&As[0][lr][lc + 4] = a1;
    *(float4*)&Bs[0][lr][lc] = b0; *(float4*)&Bs[0][lr][lc + 4] = b1;
    __syncthreads();

    const int NST = 512 / 16;   // 32 stages
    for (int s = 0; s < NST; s++) {
        int cur = s & 1;
        if (s + 1 < NST) {
            size_t oa = (size_t)(s + 1) * 16 * lda;
            size_t ob = (size_t)(s + 1) * 16 * ldb;
            a0 = *(const float4*)(pa + oa); a1 = *(const float4*)(pa + oa + 4);
            b0 = *(const float4*)(pb + ob); b1 = *(const float4*)(pb + ob + 4);
        }
        fma16(As[cur], Bs[cur], tx, ty, acc);
        if (s + 1 < NST) {
            *(float4*)&As[cur ^ 1][lr][lc] = a0; *(float4*)&As[cur ^ 1][lr][lc + 4] = a1;
            *(float4*)&Bs[cur ^ 1][lr][lc] = b0; *(float4*)&Bs[cur ^ 1][lr][lc + 4] = b1;
            __syncthreads();
        }
    }

    #pragma unroll
    for (int m = 0; m < 8; m++) {
        float* crow = Cp + (size_t)(u0 + ty * 8 + m) * ldC + v0 + tx * 8;
        #pragma unroll
        for (int n2 = 0; n2 < 4; n2++) {
            float2 v = unpack2(acc[m][n2]);
            atomicAdd(&crow[2 * n2],     v.x);
            atomicAdd(&crow[2 * n2 + 1], v.y);
        }
    }
}

// ---- pair role: symmetric ln-Gram upper-triangle tile -> denominators ----
__device__ __forceinline__ void pair_role(
    int t, float (&As)[2][16][128], float (&Bs)[2][16][128],
    int tid, int tx, int ty)
{
    int bi = 0;
    while (t >= NTILE - bi) { t -= NTILE - bi; bi++; }
    int bj = bi + t;
    int i0 = bi * 128, j0 = bj * 128;
    bool diag = (bi == bj);

    ull acc[8][4];
    #pragma unroll
    for (int m = 0; m < 8; m++)
        #pragma unroll
        for (int nn = 0; nn < 4; nn++) acc[m][nn] = 0ull;

    int lrow = tid >> 1, lkh = (tid & 1) * 8;
    const float* pa = g_ln + (size_t)(i0 + lrow) * DL + lkh;
    const float* pb = g_ln + (size_t)(j0 + lrow) * DL + lkh;

    // stage 0 (transposed store: smem is k-major)
    float4 a0 = *(const float4*)pa, a1 = *(const float4*)(pa + 4);
    float4 b0 = *(const float4*)pb, b1 = *(const float4*)(pb + 4);
    {
        float am[8] = {a0.x, a0.y, a0.z, a0.w, a1.x, a1.y, a1.z, a1.w};
        float bm[8] = {b0.x, b0.y, b0.z, b0.w, b1.x, b1.y, b1.z, b1.w};
        #pragma unroll
        for (int q = 0; q < 8; q++) {
            As[0][lkh + q][lrow] = am[q];
            Bs[0][lkh + q][lrow] = bm[q];
        }
    }
    __syncthreads();

    const int NST = DL / 16;    // 8 stages
    for (int s = 0; s < NST; s++) {
        int cur = s & 1;
        if (s + 1 < NST) {
            int ko = (s + 1) * 16;
            a0 = *(const float4*)(pa + ko); a1 = *(const float4*)(pa + ko + 4);
            b0 = *(const float4*)(pb + ko); b1 = *(const float4*)(pb + ko + 4);
        }
        fma16(As[cur], Bs[cur], tx, ty, acc);
        if (s + 1 < NST) {
            float am[8] = {a0.x, a0.y, a0.z, a0.w, a1.x, a1.y, a1.z, a1.w};
            float bm[8] = {b0.x, b0.y, b0.z, b0.w, b1.x, b1.y, b1.z, b1.w};
            #pragma unroll
            for (int q = 0; q < 8; q++) {
                As[cur ^ 1][lkh + q][lrow] = am[q];
                Bs[cur ^ 1][lkh + q][lrow] = bm[q];
            }
            __syncthreads();
        }
    }

    // epilogue: e = exp(5*sim); row sums always; col sums off-diagonal only
    float colD[8];
    #pragma unroll
    for (int n = 0; n < 8; n++) colD[n] = 0.f;

    #pragma unroll
    for (int m = 0; m < 8; m++) {
        int gi = i0 + ty * 8 + m;
        float rowD = 0.f;
        #pragma unroll
        for (int n2 = 0; n2 < 4; n2++) {
            float2 v = unpack2(acc[m][n2]);
            float e0 = __expf(v.x * 5.0f);
            float e1 = __expf(v.y * 5.0f);
            int gj0 = j0 + tx * 8 + 2 * n2;
            if (gi == gj0)     e0 = 0.f;
            if (gi == gj0 + 1) e1 = 0.f;
            rowD += e0 + e1;
            colD[2 * n2]     += e0;
            colD[2 * n2 + 1] += e1;
        }
        #pragma unroll
        for (int o = 1; o < 16; o <<= 1)
            rowD += __shfl_xor_sync(0xffffffffu, rowD, o);
        if (tx == 0) atomicAdd(&g_denom[gi], rowD);
    }

    if (!diag) {
        float* cd = &As[0][0][0];    // reuse buffer 0 (last mainloop stage read buffer 1)
        if (tid < 128) cd[tid] = 0.f;
        __syncthreads();
        #pragma unroll
        for (int n = 0; n < 8; n++) atomicAdd(&cd[tx * 8 + n], colD[n]);
        __syncthreads();
        if (tid < 128) atomicAdd(&g_denom[j0 + tid], cd[tid]);
    }
}

// ---- pos role: positive-pair dot products ----
__device__ __forceinline__ void pos_role(int pb, int tid) {
    int n = g_npairs; if (n > MAXPAIRS) n = MAXPAIRS;
    int gw = (pb * 256 + tid) >> 5;
    int lane = tid & 31;
    const int NW = (NB_POS * 256) >> 5;
    for (int p = gw; p < n; p += NW) {
        int code = g_pairs[p];
        int i = code >> 12, j = code & 4095;
        float4 x = ((const float4*)(g_ln + (size_t)i * DL))[lane];
        float4 y = ((const float4*)(g_ln + (size_t)j * DL))[lane];
        float s = x.x * y.x + x.y * y.y + x.z * y.z + x.w * y.w;
        #pragma unroll
        for (int o = 16; o; o >>= 1) s += __shfl_xor_sync(0xffffffffu, s, o);
        if (!lane) {
            atomicAdd(&g_possum[i], s * 5.0f);
            atomicAdd(&g_cnt[i], 1.0f);
        }
    }
}

// ---- mega kernel dispatch ----
__global__ void __launch_bounds__(256, 2) mega_kernel(const float* __restrict__ hash) {
    __shared__ float As[2][16][128];
    __shared__ float Bs[2][16][128];
    int tid = threadIdx.x, tx = tid & 15, ty = tid >> 4;
    int b = blockIdx.x;
    if (b < NB_GRAM)                 gram_role(b, hash, As, Bs, tid, tx, ty);
    else if (b < NB_GRAM + NB_PAIR)  pair_role(b - NB_GRAM, As, Bs, tid, tx, ty);
    else                             pos_role(b - NB_GRAM - NB_PAIR, tid);
}

// ---------------- kernel: weighted squared-Frobenius reduction -----------
__global__ void square_kernel() {
    int i = blockIdx.x * blockDim.x + threadIdx.x;
    float vTT = 0.f, vTH = 0.f, vHH = 0.f;
    if (i < C_TT_SZ) {
        float c = g_C[i];
        int u = i / 768, v = i - u * 768;
        int tu = u >> 7, tv = v >> 7;
        float w = (tv > tu) ? 2.f : ((tv == tu) ? 1.f : 0.f);
        vTT = w * c * c;
    } else if (i < C_HH_OFF) {
        float c = g_C[i]; vTH = c * c;
    } else if (i < C_TOTAL) {
        float c = g_C[i]; vHH = c * c;
    }
    #pragma unroll
    for (int o = 16; o; o >>= 1) {
        vTT += __shfl_xor_sync(0xffffffffu, vTT, o);
        vTH += __shfl_xor_sync(0xffffffffu, vTH, o);
        vHH += __shfl_xor_sync(0xffffffffu, vHH, o);
    }
    __shared__ float sh[3][8];
    int lane = threadIdx.x & 31, wid = threadIdx.x >> 5;
    if (!lane) { sh[0][wid] = vTT; sh[1][wid] = vTH; sh[2][wid] = vHH; }
    __syncthreads();
    if (threadIdx.x < 3) {
        float s = 0.f;
        #pragma unroll
        for (int w = 0; w < 8; w++) s += sh[threadIdx.x][w];
        if (s != 0.f) atomicAdd(&g_scal[2 + threadIdx.x], s);
    }
}

// ---------------- kernel: finalize ----------------
__global__ void finalize_kernel(float* __restrict__ out) {
    int tid = threadIdx.x;
    float local = 0.f, np = 0.f;
    for (int r = tid; r < B; r += 256) {
        float c = g_cnt[r];
        if (c > 0.f) {
            local += logf(g_denom[r]) - g_possum[r] / c;
            np += 1.f;
        }
    }
    __shared__ float sred[256];
    __shared__ float snp[256];
    sred[tid] = local; snp[tid] = np;
    __syncthreads();
    for (int s = 128; s; s >>= 1) {
        if (tid < s) { sred[tid] += sred[tid + s]; snp[tid] += snp[tid + s]; }
        __syncthreads();
    }
    if (!tid) {
        float cont = sred[0] / fmaxf(snp[0], 1.0f);
        float distill_sum = g_scal[4] * (1.0f / 16384.0f)
                          - g_scal[3] * (1.0f / 64.0f)
                          + g_scal[2];
        float distill = distill_sum / ((float)B * (float)B);
        float quant = g_scal[1] / ((float)B * (float)DL);
        out[0] = cont + 0.5f * distill + 0.01f * quant;
    }
}

// ---------------- entry point ----------------
extern "C" void kernel_launch(void* const* d_in, const int* in_sizes, int n_in,
                              void* d_out, int out_size) {
    const float* logits  = (const float*)d_in[0];
    const float* hash    = (const float*)d_in[1];
    const float* teacher = (const float*)d_in[2];
    const int*   mask    = (const int*)d_in[3];   // bool stored 4-byte; nonzero test
    float* out = (float*)d_out;

    zero_kernel<<<(C_TOTAL + 255) / 256, 256>>>();
    norm_logits_kernel<<<B, 128>>>(logits);
    norm_teacher_kernel<<<B, 256>>>(teacher);
    extract_kernel<<<(B * B) / (256 * 32), 256>>>(mask);
    mega_kernel<<<NB_GRAM + NB_PAIR + NB_POS, 256>>>(hash);
    square_kernel<<<(C_TOTAL + 255) / 256, 256>>>();
    finalize_kernel<<<1, 256>>>(out);
}

// round 5
// speedup vs baseline: 4.0787x; 1.0188x over previous
#include <cuda_runtime.h>

#define B   4096
#define DL  128
#define DT  768
#define NTILE 32                         // B / 128

#define C_TT_SZ  (768*768)
#define C_TH_SZ  (768*128)
#define C_HH_SZ  (128*128)
#define C_TH_OFF (C_TT_SZ)
#define C_HH_OFF (C_TT_SZ + C_TH_SZ)
#define C_TOTAL  (C_TT_SZ + C_TH_SZ + C_HH_SZ)   // 704512

// mega-kernel role partition
#define NB_TT   168      // 21 upper-tri tiles x 8 k-chunks
#define NB_TH   48       // 6 tiles x 8 k-chunks
#define NB_HH   8        // 1 tile x 8 k-chunks
#define NB_GRAM (NB_TT + NB_TH + NB_HH)          // 224
#define NB_PAIR 528

typedef unsigned long long ull;

// ---------------- device scratch ----------------
__device__ float g_lnT[DL * B];    // normalized logits, TRANSPOSED: [feature][batch]
__device__ float g_tn[B * DT];     // normalized teacher, row-major (= k-major for gram)
__device__ float g_C[C_TOTAL];
__device__ float g_denom[B];
__device__ float g_possum[B];
__device__ float g_cnt[B];
__device__ float g_scal[8];        // [2]=G_TT, [3]=G_TH, [4]=G_HH
__device__ float g_qpart[128];     // per-block quant partials

// ---------------- packed f32x2 helpers ----------------
__device__ __forceinline__ ull pack2(float lo, float hi) {
    ull r; asm("mov.b64 %0, {%1, %2};" : "=l"(r) : "f"(lo), "f"(hi)); return r;
}
__device__ __forceinline__ float2 unpack2(ull v) {
    float2 r; asm("mov.b64 {%0, %1}, %2;" : "=f"(r.x), "=f"(r.y) : "l"(v)); return r;
}
#define FMA2(d, a, b) asm("fma.rn.f32x2 %0, %1, %2, %0;" : "+l"(d) : "l"(a), "l"(b))

// 16 k-slices: A from duplicated-pair smem (no movs), B as raw f32 pairs (no movs)
__device__ __forceinline__ void fma16(const ull (&Ad)[16][128], const float (&Bs)[16][128],
                                      int tx, int ty, ull (&acc)[8][4]) {
    #pragma unroll
    for (int k = 0; k < 16; k++) {
        const ull* ap = &Ad[k][ty * 8];
        ulonglong2 av0 = *(const ulonglong2*)(ap);
        ulonglong2 av1 = *(const ulonglong2*)(ap + 2);
        ulonglong2 av2 = *(const ulonglong2*)(ap + 4);
        ulonglong2 av3 = *(const ulonglong2*)(ap + 6);
        const ull* bp = (const ull*)&Bs[k][tx * 8];
        ulonglong2 bv0 = *(const ulonglong2*)(bp);
        ulonglong2 bv1 = *(const ulonglong2*)(bp + 2);
        ull a[8] = {av0.x, av0.y, av1.x, av1.y, av2.x, av2.y, av3.x, av3.y};
        ull b[4] = {bv0.x, bv0.y, bv1.x, bv1.y};
        #pragma unroll
        for (int m = 0; m < 8; m++) {
            FMA2(acc[m][0], a[m], b[0]);
            FMA2(acc[m][1], a[m], b[1]);
            FMA2(acc[m][2], a[m], b[2]);
            FMA2(acc[m][3], a[m], b[3]);
        }
    }
}

__device__ __forceinline__ void store_stage(ull (&Ad)[16][128], float (&Bs)[16][128],
                                            int lr, int lc,
                                            float4 a0, float4 a1, float4 b0, float4 b1) {
    ulonglong2 d;
    d.x = pack2(a0.x, a0.x); d.y = pack2(a0.y, a0.y);
    *(ulonglong2*)&Ad[lr][lc]     = d;
    d.x = pack2(a0.z, a0.z); d.y = pack2(a0.w, a0.w);
    *(ulonglong2*)&Ad[lr][lc + 2] = d;
    d.x = pack2(a1.x, a1.x); d.y = pack2(a1.y, a1.y);
    *(ulonglong2*)&Ad[lr][lc + 4] = d;
    d.x = pack2(a1.z, a1.z); d.y = pack2(a1.w, a1.w);
    *(ulonglong2*)&Ad[lr][lc + 6] = d;
    *(float4*)&Bs[lr][lc]     = b0;
    *(float4*)&Bs[lr][lc + 4] = b1;
}

// double-buffered k-major mainloop: acc += A[k, u0+..128)^T B[k, v0+..128)
__device__ __forceinline__ void mainloop(const float* __restrict__ pa,
                                         const float* __restrict__ pb,
                                         int lda, int ldb, int nst,
                                         ull (&Ad)[2][16][128], float (&Bs)[2][16][128],
                                         int tid, int tx, int ty, ull (&acc)[8][4]) {
    int lr = tid >> 4, lc = (tid & 15) * 8;
    pa += (size_t)lr * lda + lc;
    pb += (size_t)lr * ldb + lc;
    float4 a0 = *(const float4*)pa, a1 = *(const float4*)(pa + 4);
    float4 b0 = *(const float4*)pb, b1 = *(const float4*)(pb + 4);
    store_stage(Ad[0], Bs[0], lr, lc, a0, a1, b0, b1);
    __syncthreads();
    for (int s = 0; s < nst; s++) {
        int cur = s & 1;
        if (s + 1 < nst) {
            const float* qa = pa + (size_t)(s + 1) * 16 * lda;
            const float* qb = pb + (size_t)(s + 1) * 16 * ldb;
            a0 = *(const float4*)qa; a1 = *(const float4*)(qa + 4);
            b0 = *(const float4*)qb; b1 = *(const float4*)(qb + 4);
        }
        fma16(Ad[cur], Bs[cur], tx, ty, acc);
        if (s + 1 < nst) {
            store_stage(Ad[cur ^ 1], Bs[cur ^ 1], lr, lc, a0, a1, b0, b1);
            __syncthreads();
        }
    }
}

// ---------------- prep: zero scratch + normalize logits (transposed) + quant ----
__global__ void __launch_bounds__(256) prep_kernel(const float* __restrict__ logits) {
    __shared__ float S[32][129];
    __shared__ float rinv[32];
    __shared__ float qsh[8];
    int blk = blockIdx.x, tid = threadIdx.x;
    int lane = tid & 31, w = tid >> 5;
    int r0 = blk * 32;

    float q = 0.f;
    #pragma unroll
    for (int it = 0; it < 16; it++) {
        int idx = tid + it * 256;
        float x = logits[r0 * DL + idx];
        S[idx >> 7][idx & 127] = x;
        q += fabsf(fabsf(x) - 1.0f);
    }
    // zero global scratch (this kernel precedes all consumers)
    for (int i = blk * 256 + tid; i < C_TOTAL; i += 128 * 256) g_C[i] = 0.f;
    if (tid < 32) {
        int i = r0 + tid;
        g_denom[i] = 0.f; g_possum[i] = 0.f; g_cnt[i] = 0.f;
    }
    if (tid < 8) g_scal[tid] = 0.f;   // every block writes 0: benign
    __syncthreads();

    // row norms: warp w handles rows 4w..4w+3
    for (int rr = 0; rr < 4; rr++) {
        int r = w * 4 + rr;
        float v0 = S[r][lane], v1 = S[r][lane + 32], v2 = S[r][lane + 64], v3 = S[r][lane + 96];
        float ss = v0 * v0 + v1 * v1 + v2 * v2 + v3 * v3;
        #pragma unroll
        for (int o = 16; o; o >>= 1) ss += __shfl_xor_sync(0xffffffffu, ss, o);
        if (!lane) rinv[r] = 1.0f / fmaxf(sqrtf(ss), 1e-12f);
    }
    __syncthreads();

    // write transposed normalized logits: thread -> feature f, 16-batch half h
    {
        int f = tid >> 1, h = tid & 1;
        float out[16];
        #pragma unroll
        for (int i = 0; i < 16; i++) {
            int r = h * 16 + i;
            out[i] = S[r][f] * rinv[r];
        }
        float* dst = g_lnT + (size_t)f * B + r0 + h * 16;
        #pragma unroll
        for (int i = 0; i < 4; i++)
            *(float4*)(dst + i * 4) = make_float4(out[i*4], out[i*4+1], out[i*4+2], out[i*4+3]);
    }

    // quant partial per block (no atomic)
    #pragma unroll
    for (int o = 16; o; o >>= 1) q += __shfl_xor_sync(0xffffffffu, q, o);
    if (!lane) qsh[w] = q;
    __syncthreads();
    if (!tid) {
        float s = 0.f;
        #pragma unroll
        for (int i = 0; i < 8; i++) s += qsh[i];
        g_qpart[blk] = s;
    }
}

// ---------------- normalize teacher ----------------
__global__ void norm_teacher_kernel(const float* __restrict__ t) {
    int row = blockIdx.x, tid = threadIdx.x;
    int lane = tid & 31, wid = tid >> 5;
    const float* p = t + (size_t)row * DT;
    float x0 = p[tid], x1 = p[tid + 256], x2 = p[tid + 512];
    float ss = x0 * x0 + x1 * x1 + x2 * x2;
    #pragma unroll
    for (int o = 16; o; o >>= 1) ss += __shfl_xor_sync(0xffffffffu, ss, o);
    __shared__ float sh[8];
    if (!lane) sh[wid] = ss;
    __syncthreads();
    float tot = 0.f;
    #pragma unroll
    for (int w = 0; w < 8; w++) tot += sh[w];
    float inv = 1.0f / fmaxf(sqrtf(tot), 1e-12f);
    float* o = g_tn + (size_t)row * DT;
    o[tid] = x0 * inv; o[tid + 256] = x1 * inv; o[tid + 512] = x2 * inv;
}

// ======================= mega kernel roles =======================

// ---- gram role: split-K tall-skinny Grams (k = batch row, so inputs are k-major) ----
__device__ __forceinline__ void gram_role(
    int jid, const float* __restrict__ hash,
    ull (&Ad)[2][16][128], float (&Bs)[2][16][128],
    int tid, int tx, int ty)
{
    const float *A, *Bm; int lda, ldb, u0, v0, kbase, ldC; float* Cp;
    if (jid < NB_TT) {                     // TT upper triangle of 6x6 tiles
        int t = jid >> 3, chunk = jid & 7;
        int tu = 0;
        while (t >= 6 - tu) { t -= 6 - tu; tu++; }
        int tv = tu + t;
        A = g_tn; Bm = g_tn; lda = DT; ldb = DT;
        u0 = tu * 128; v0 = tv * 128;
        Cp = g_C; ldC = DT; kbase = chunk * 512;
    } else if (jid < NB_TT + NB_TH) {      // TH
        int r = jid - NB_TT;
        int t = r >> 3, chunk = r & 7;
        A = g_tn; Bm = hash; lda = DT; ldb = DL;
        u0 = t * 128; v0 = 0;
        Cp = g_C + C_TH_OFF; ldC = DL; kbase = chunk * 512;
    } else {                               // HH
        int chunk = jid - NB_TT - NB_TH;
        A = hash; Bm = hash; lda = DL; ldb = DL;
        u0 = 0; v0 = 0;
        Cp = g_C + C_HH_OFF; ldC = DL; kbase = chunk * 512;
    }

    ull acc[8][4];
    #pragma unroll
    for (int m = 0; m < 8; m++)
        #pragma unroll
        for (int nn = 0; nn < 4; nn++) acc[m][nn] = 0ull;

    mainloop(A + (size_t)kbase * lda + u0, Bm + (size_t)kbase * ldb + v0,
             lda, ldb, 32, Ad, Bs, tid, tx, ty, acc);

    #pragma unroll
    for (int m = 0; m < 8; m++) {
        float* crow = Cp + (size_t)(u0 + ty * 8 + m) * ldC + v0 + tx * 8;
        #pragma unroll
        for (int n2 = 0; n2 < 4; n2++) {
            float2 v = unpack2(acc[m][n2]);
            atomicAdd(&crow[2 * n2],     v.x);
            atomicAdd(&crow[2 * n2 + 1], v.y);
        }
    }
}

// ---- pair role: symmetric ln-Gram tile -> denom + mask-fused possum/cnt ----
__device__ __forceinline__ void pair_role(
    int t, const int* __restrict__ mask,
    ull (&Ad)[2][16][128], float (&Bs)[2][16][128],
    int tid, int tx, int ty)
{
    int bi = 0;
    while (t >= NTILE - bi) { t -= NTILE - bi; bi++; }
    int bj = bi + t;
    int i0 = bi * 128, j0 = bj * 128;
    bool diag = (bi == bj);

    ull acc[8][4];
    #pragma unroll
    for (int m = 0; m < 8; m++)
        #pragma unroll
        for (int nn = 0; nn < 4; nn++) acc[m][nn] = 0ull;

    // g_lnT is [feature][batch] -> k-major, same loader as gram
    mainloop(g_lnT + i0, g_lnT + j0, B, B, DL / 16, Ad, Bs, tid, tx, ty, acc);

    float colD[8], colP[8], colC[8];
    #pragma unroll
    for (int n = 0; n < 8; n++) { colD[n] = 0.f; colP[n] = 0.f; colC[n] = 0.f; }

    // row side: denom + mask(i,j) possum/cnt
    #pragma unroll
    for (int m = 0; m < 8; m++) {
        int gi = i0 + ty * 8 + m;
        const int4* mp = (const int4*)(mask + (size_t)gi * B + j0 + tx * 8);
        int4 mv0 = __ldcs(mp);
        int4 mv1 = __ldcs(mp + 1);
        int mv[8] = {mv0.x, mv0.y, mv0.z, mv0.w, mv1.x, mv1.y, mv1.z, mv1.w};
        float rowD = 0.f, rowP = 0.f, rowC = 0.f;
        #pragma unroll
        for (int n2 = 0; n2 < 4; n2++) {
            float2 v = unpack2(acc[m][n2]);
            float s0 = v.x * 5.0f, s1 = v.y * 5.0f;   // / TEMPERATURE
            int gj0 = j0 + tx * 8 + 2 * n2;
            float e0 = __expf(s0), e1 = __expf(s1);
            if (gi == gj0)     e0 = 0.f;    // diag excluded from denom only
            if (gi == gj0 + 1) e1 = 0.f;
            rowD += e0 + e1;
            colD[2 * n2]     += e0;
            colD[2 * n2 + 1] += e1;
            if (mv[2 * n2])     { rowP += s0; rowC += 1.f; }
            if (mv[2 * n2 + 1]) { rowP += s1; rowC += 1.f; }
        }
        #pragma unroll
        for (int o = 1; o < 16; o <<= 1) {
            rowD += __shfl_xor_sync(0xffffffffu, rowD, o);
            rowP += __shfl_xor_sync(0xffffffffu, rowP, o);
            rowC += __shfl_xor_sync(0xffffffffu, rowC, o);
        }
        if (tx == 0) {
            atomicAdd(&g_denom[gi], rowD);
            if (rowC != 0.f) {
                atomicAdd(&g_possum[gi], rowP);
                atomicAdd(&g_cnt[gi], rowC);
            }
        }
    }

    // column side (off-diagonal tiles only): denom(j) + mask(j,i) possum/cnt via sim(j,i)=sim(i,j)
    if (!diag) {
        #pragma unroll
        for (int n = 0; n < 8; n++) {
            int gj = j0 + tx * 8 + n;
            const int4* mp = (const int4*)(mask + (size_t)gj * B + i0 + ty * 8);
            int4 mu0 = __ldcs(mp);
            int4 mu1 = __ldcs(mp + 1);
            int mu[8] = {mu0.x, mu0.y, mu0.z, mu0.w, mu1.x, mu1.y, mu1.z, mu1.w};
            #pragma unroll
            for (int m = 0; m < 8; m++) {
                if (mu[m]) {
                    float2 v = unpack2(acc[m][n >> 1]);
                    float s = ((n & 1) ? v.y : v.x) * 5.0f;
                    colP[n] += s; colC[n] += 1.f;
                }
            }
        }
        float* cd = (float*)&Ad[0][0][0];
        float* cp = cd + 128;
        float* cc = cd + 256;
        __syncthreads();
        if (tid < 128) { cd[tid] = 0.f; cp[tid] = 0.f; cc[tid] = 0.f; }
        __syncthreads();
        #pragma unroll
        for (int n = 0; n < 8; n++) {
            atomicAdd(&cd[tx * 8 + n], colD[n]);
            if (colC[n] != 0.f) {
                atomicAdd(&cp[tx * 8 + n], colP[n]);
                atomicAdd(&cc[tx * 8 + n], colC[n]);
            }
        }
        __syncthreads();
        if (tid < 128) {
            atomicAdd(&g_denom[j0 + tid], cd[tid]);
            float c = cc[tid];
            if (c != 0.f) {
                atomicAdd(&g_possum[j0 + tid], cp[tid]);
                atomicAdd(&g_cnt[j0 + tid], c);
            }
        }
    }
}

// ---- mega kernel dispatch ----
__global__ void __launch_bounds__(256, 2) mega_kernel(const float* __restrict__ hash,
                                                      const int* __restrict__ mask) {
    __shared__ ull   Ad[2][16][128];   // 32 KB: duplicated A pairs
    __shared__ float Bss[2][16][128];  // 16 KB
    int tid = threadIdx.x, tx = tid & 15, ty = tid >> 4;
    int b = blockIdx.x;
    if (b < NB_GRAM) gram_role(b, hash, Ad, Bss, tid, tx, ty);
    else             pair_role(b - NB_GRAM, mask, Ad, Bss, tid, tx, ty);
}

// ---------------- weighted squared-Frobenius reduction ----------------
__global__ void square_kernel() {
    int i = blockIdx.x * blockDim.x + threadIdx.x;
    float vTT = 0.f, vTH = 0.f, vHH = 0.f;
    if (i < C_TT_SZ) {
        float c = g_C[i];
        int u = i / 768, v = i - u * 768;
        int tu = u >> 7, tv = v >> 7;
        float w = (tv > tu) ? 2.f : ((tv == tu) ? 1.f : 0.f);
        vTT = w * c * c;
    } else if (i < C_HH_OFF) {
        float c = g_C[i]; vTH = c * c;
    } else if (i < C_TOTAL) {
        float c = g_C[i]; vHH = c * c;
    }
    #pragma unroll
    for (int o = 16; o; o >>= 1) {
        vTT += __shfl_xor_sync(0xffffffffu, vTT, o);
        vTH += __shfl_xor_sync(0xffffffffu, vTH, o);
        vHH += __shfl_xor_sync(0xffffffffu, vHH, o);
    }
    __shared__ float sh[3][8];
    int lane = threadIdx.x & 31, wid = threadIdx.x >> 5;
    if (!lane) { sh[0][wid] = vTT; sh[1][wid] = vTH; sh[2][wid] = vHH; }
    __syncthreads();
    if (threadIdx.x < 3) {
        float s = 0.f;
        #pragma unroll
        for (int w = 0; w < 8; w++) s += sh[threadIdx.x][w];
        if (s != 0.f) atomicAdd(&g_scal[2 + threadIdx.x], s);
    }
}

// ---------------- finalize ----------------
__global__ void finalize_kernel(float* __restrict__ out) {
    int tid = threadIdx.x;
    float local = 0.f, np = 0.f;
    for (int r = tid; r < B; r += 256) {
        float c = g_cnt[r];
        if (c > 0.f) {
            local += logf(g_denom[r]) - g_possum[r] / c;
            np += 1.f;
        }
    }
    float qs = (tid < 128) ? g_qpart[tid] : 0.f;
    __shared__ float s1[256], s2[256], s3[256];
    s1[tid] = local; s2[tid] = np; s3[tid] = qs;
    __syncthreads();
    for (int s = 128; s; s >>= 1) {
        if (tid < s) { s1[tid] += s1[tid + s]; s2[tid] += s2[tid + s]; s3[tid] += s3[tid + s]; }
        __syncthreads();
    }
    if (!tid) {
        float cont = s1[0] / fmaxf(s2[0], 1.0f);
        float distill_sum = g_scal[4] * (1.0f / 16384.0f)
                          - g_scal[3] * (1.0f / 64.0f)
                          + g_scal[2];
        float distill = distill_sum / ((float)B * (float)B);
        float quant = s3[0] / ((float)B * (float)DL);
        out[0] = cont + 0.5f * distill + 0.01f * quant;
    }
}

// ---------------- entry point ----------------
extern "C" void kernel_launch(void* const* d_in, const int* in_sizes, int n_in,
                              void* d_out, int out_size) {
    const float* logits  = (const float*)d_in[0];
    const float* hash    = (const float*)d_in[1];
    const float* teacher = (const float*)d_in[2];
    const int*   mask    = (const int*)d_in[3];   // bool stored 4-byte; nonzero test
    float* out = (float*)d_out;

    prep_kernel<<<128, 256>>>(logits);
    norm_teacher_kernel<<<B, 256>>>(teacher);
    mega_kernel<<<NB_GRAM + NB_PAIR, 256>>>(hash, mask);
    square_kernel<<<(C_TOTAL + 255) / 256, 256>>>();
    finalize_kernel<<<1, 256>>>(out);
}

// round 8
// speedup vs baseline: 9.9538x; 2.4405x over previous
#include <cuda_runtime.h>
#include <cuda_bf16.h>

#define B   4096
#define DL  128
#define DT  768

#define C_TT_SZ  (768*768)
#define C_TH_SZ  (768*128)
#define C_HH_SZ  (128*128)
#define C_TH_OFF (C_TT_SZ)
#define C_HH_OFF (C_TT_SZ + C_TH_SZ)
#define C_TOTAL  (C_TT_SZ + C_TH_SZ + C_HH_SZ)   // 704512

#define NB_GRAM 112     // TT 21*4 + TH 6*4 + HH 1*4 (split-K over batch)
#define NB_PAIR 1024
#define KC 64
#define SST 72          // smem row stride in bf16 (144 B: ldmatrix conflict-free)

typedef unsigned int uint;

// ---------------- device scratch ----------------
__device__ __nv_bfloat16 g_lnb[B * DL];      // normalized logits bf16, row-major [batch][feat]
__device__ __nv_bfloat16 g_tnT[DT * B];      // normalized teacher bf16, [feat][batch]
__device__ __nv_bfloat16 g_hT[DL * B];       // hash bf16, [feat][batch]
__device__ float g_C4[4 * C_TOTAL];          // split-K gram slabs (plain stores)
__device__ float g_denom[B];
__device__ float g_possum[B];
__device__ float g_cnt[B];
__device__ float g_scal[8];                  // [2]=G_TT [3]=G_TH [4]=G_HH
__device__ float g_qpart[128];

// ---------------- helpers ----------------
__device__ __forceinline__ uint smem_u32(const void* p) {
    uint a;
    asm("{ .reg .u64 t; cvta.to.shared.u64 t, %1; cvt.u32.u64 %0, t; }" : "=r"(a) : "l"(p));
    return a;
}
__device__ __forceinline__ void ldm4(uint& r0, uint& r1, uint& r2, uint& r3, uint addr) {
    asm volatile("ldmatrix.sync.aligned.m8n8.x4.shared.b16 {%0,%1,%2,%3}, [%4];"
                 : "=r"(r0), "=r"(r1), "=r"(r2), "=r"(r3) : "r"(addr));
}
__device__ __forceinline__ void mma16816(float* c, const uint* a, uint b0, uint b1) {
    asm volatile("mma.sync.aligned.m16n8k16.row.col.f32.bf16.bf16.f32 "
        "{%0,%1,%2,%3}, {%4,%5,%6,%7}, {%8,%9}, {%0,%1,%2,%3};"
        : "+f"(c[0]), "+f"(c[1]), "+f"(c[2]), "+f"(c[3])
        : "r"(a[0]), "r"(a[1]), "r"(a[2]), "r"(a[3]), "r"(b0), "r"(b1));
}
__device__ __forceinline__ uint bf2(float lo, float hi) {
    __nv_bfloat162 p = __floats2bfloat162_rn(lo, hi);
    return *(uint*)&p;
}

// ---------------- prep: logits normalize->bf16 rows, hash transpose->bf16, quant ----
__global__ void __launch_bounds__(256) prep_lh(const float* __restrict__ logits,
                                               const float* __restrict__ hash) {
    __shared__ float S[32][129];
    __shared__ float H[32][129];
    __shared__ float rinv[32];
    __shared__ float qsh[8];
    int blk = blockIdx.x, tid = threadIdx.x;
    int lane = tid & 31, w = tid >> 5;
    int r0 = blk * 32;

    float q = 0.f;
    #pragma unroll
    for (int it = 0; it < 16; it++) {
        int idx = tid + it * 256;
        int row = idx >> 7, f = idx & 127;
        float x = logits[(size_t)(r0 + row) * DL + f];
        S[row][f] = x;
        q += fabsf(fabsf(x) - 1.0f);
        H[row][f] = hash[(size_t)(r0 + row) * DL + f];
    }
    if (tid < 32) {
        int i = r0 + tid;
        g_denom[i] = 0.f; g_possum[i] = 0.f; g_cnt[i] = 0.f;
    }
    if (blk == 0 && tid < 8) g_scal[tid] = 0.f;
    __syncthreads();

    #pragma unroll
    for (int rr = 0; rr < 4; rr++) {
        int r = w * 4 + rr;
        float v0 = S[r][lane], v1 = S[r][lane + 32], v2 = S[r][lane + 64], v3 = S[r][lane + 96];
        float ss = v0 * v0 + v1 * v1 + v2 * v2 + v3 * v3;
        #pragma unroll
        for (int o = 16; o; o >>= 1) ss += __shfl_xor_sync(0xffffffffu, ss, o);
        if (!lane) rinv[r] = 1.0f / fmaxf(sqrtf(ss), 1e-12f);
    }
    __syncthreads();

    {   // normalized bf16 rows: 8 threads per row, 16 feats per thread (FIXED: was tid>>1 OOB)
        int row = tid >> 3, f0 = (tid & 7) * 16;
        float riv = rinv[row];
        uint out[8];
        #pragma unroll
        for (int c = 0; c < 8; c++)
            out[c] = bf2(S[row][f0 + 2 * c] * riv, S[row][f0 + 2 * c + 1] * riv);
        uint4* dst = (uint4*)(g_lnb + (size_t)(r0 + row) * DL + f0);
        dst[0] = make_uint4(out[0], out[1], out[2], out[3]);
        dst[1] = make_uint4(out[4], out[5], out[6], out[7]);
    }

    {   // hash transpose bf16: thread -> (feature, 16-batch half)
        int f = tid & 127, h = tid >> 7;
        uint out[8];
        #pragma unroll
        for (int i = 0; i < 8; i++)
            out[i] = bf2(H[h * 16 + 2 * i][f], H[h * 16 + 2 * i + 1][f]);
        uint4* dst = (uint4*)(g_hT + (size_t)f * B + r0 + h * 16);
        dst[0] = make_uint4(out[0], out[1], out[2], out[3]);
        dst[1] = make_uint4(out[4], out[5], out[6], out[7]);
    }

    #pragma unroll
    for (int o = 16; o; o >>= 1) q += __shfl_xor_sync(0xffffffffu, q, o);
    if (!lane) qsh[w] = q;
    __syncthreads();
    if (!tid) {
        float s = 0.f;
        #pragma unroll
        for (int i = 0; i < 8; i++) s += qsh[i];
        g_qpart[blk] = s;
    }
}

// ---------------- prep: teacher normalize -> bf16 transposed [feat][batch] ----
__global__ void __launch_bounds__(256) prep_teacher(const float* __restrict__ t) {
    __shared__ float S[32][129];
    __shared__ float rinv[32];
    int blk = blockIdx.x, tid = threadIdx.x;
    int lane = tid & 31, w = tid >> 5;
    int r0 = blk * 32;

    #pragma unroll
    for (int rr = 0; rr < 4; rr++) {
        int r = w * 4 + rr;
        const float* p = t + (size_t)(r0 + r) * DT;
        float ss = 0.f;
        #pragma unroll
        for (int u = 0; u < 24; u++) { float x = p[lane + u * 32]; ss += x * x; }
        #pragma unroll
        for (int o = 16; o; o >>= 1) ss += __shfl_xor_sync(0xffffffffu, ss, o);
        if (!lane) rinv[r] = 1.0f / fmaxf(sqrtf(ss), 1e-12f);
    }
    __syncthreads();

    for (int chunk = 0; chunk < 6; chunk++) {
        int f0 = chunk * 128;
        #pragma unroll
        for (int it = 0; it < 16; it++) {
            int idx = tid + it * 256;
            int row = idx >> 7, f = idx & 127;
            S[row][f] = t[(size_t)(r0 + row) * DT + f0 + f];
        }
        __syncthreads();
        int f = tid & 127, h = tid >> 7;
        uint out[8];
        #pragma unroll
        for (int i = 0; i < 8; i++) {
            int ra = h * 16 + 2 * i, rb = ra + 1;
            out[i] = bf2(S[ra][f] * rinv[ra], S[rb][f] * rinv[rb]);
        }
        uint4* dst = (uint4*)(g_tnT + (size_t)(f0 + f) * B + r0 + h * 16);
        dst[0] = make_uint4(out[0], out[1], out[2], out[3]);
        dst[1] = make_uint4(out[4], out[5], out[6], out[7]);
        __syncthreads();
    }
}

// ---------------- mega: all Grams via mma.sync bf16 ----------------
__global__ void __launch_bounds__(256) mega_kernel(const int* __restrict__ mask) {
    __shared__ __align__(16) __nv_bfloat16 smA[128 * SST];   // 18432 B
    __shared__ __align__(16) __nv_bfloat16 smB[128 * SST];   // 18432 B

    int tid = threadIdx.x, lane = tid & 31, wid = tid >> 5;
    int wm = wid & 1, wn = wid >> 1;       // warp tile (64 x 32) at (wm*64, wn*32)
    int b = blockIdx.x;

    const __nv_bfloat16 *srcA, *srcB;
    size_t ldA, ldB;
    int nchunk, role;
    int u0 = 0, v0 = 0, ldC = 0;
    float* cslab = 0;
    int i0 = 0, j0 = 0;

    if (b < NB_GRAM) {
        role = 0;
        int kchunk;
        if (b < 84) {                       // TT upper triangle (21 tiles x 4 k-chunks)
            int tt = b >> 2; kchunk = b & 3;
            int tu = 0;
            while (tt >= 6 - tu) { tt -= 6 - tu; tu++; }
            int tv = tu + tt;
            u0 = tu * 128; v0 = tv * 128;
            srcA = g_tnT + (size_t)u0 * B; srcB = g_tnT + (size_t)v0 * B;
            cslab = g_C4 + (size_t)kchunk * C_TOTAL; ldC = 768;
        } else if (b < 108) {               // TH (6 tiles x 4)
            int r = b - 84; int tt = r >> 2; kchunk = r & 3;
            u0 = tt * 128; v0 = 0;
            srcA = g_tnT + (size_t)u0 * B; srcB = g_hT;
            cslab = g_C4 + (size_t)kchunk * C_TOTAL + C_TH_OFF; ldC = 128;
        } else {                            // HH (1 tile x 4)
            kchunk = b - 108;
            srcA = g_hT; srcB = g_hT;
            cslab = g_C4 + (size_t)kchunk * C_TOTAL + C_HH_OFF; ldC = 128;
        }
        srcA += (size_t)kchunk * 1024;
        srcB += (size_t)kchunk * 1024;
        ldA = B; ldB = B;
        nchunk = 1024 / KC;                 // 16
    } else {
        role = 1;
        int idx = b - NB_GRAM;
        i0 = (idx >> 5) * 128; j0 = (idx & 31) * 128;
        srcA = g_lnb + (size_t)i0 * DL;
        srcB = g_lnb + (size_t)j0 * DL;
        ldA = DL; ldB = DL;
        nchunk = DL / KC;                   // 2
    }

    float c[4][4][4];
    #pragma unroll
    for (int i = 0; i < 4; i++)
        #pragma unroll
        for (int j = 0; j < 4; j++)
            #pragma unroll
            for (int e = 0; e < 4; e++) c[i][j][e] = 0.f;

    uint smA32 = smem_u32(smA), smB32 = smem_u32(smB);
    int g = lane >> 3, lr = lane & 7;
    // A frag addresses (row-major m16k16): matrices [m0-7,k0][m8-15,k0][m0-7,k8][m8-15,k8]
    uint abase = smA32 + (uint)(((wm * 64 + ((g & 1) << 3) + lr) * SST + ((g >> 1) << 3)) * 2);
    // B frag addresses: matrices [n0-7,k0][n0-7,k8][n8-15,k0][n8-15,k8]
    uint bbase = smB32 + (uint)(((wn * 32 + ((g >> 1) << 3) + lr) * SST + ((g & 1) << 3)) * 2);

    int lrow = tid >> 1, lh = (tid & 1) * 32;   // loader: row, 32-bf16 half
    const __nv_bfloat16* pa = srcA + (size_t)lrow * ldA + lh;
    const __nv_bfloat16* pb = srcB + (size_t)lrow * ldB + lh;
    uint4* sa  = (uint4*)(smA + lrow * SST + lh);
    uint4* sbp = (uint4*)(smB + lrow * SST + lh);

    for (int cch = 0; cch < nchunk; cch++) {
        const uint4* ga = (const uint4*)(pa + cch * KC);
        const uint4* gb = (const uint4*)(pb + cch * KC);
        uint4 ra0 = ga[0], ra1 = ga[1], ra2 = ga[2], ra3 = ga[3];
        uint4 rb0 = gb[0], rb1 = gb[1], rb2 = gb[2], rb3 = gb[3];
        __syncthreads();
        sa[0] = ra0; sa[1] = ra1; sa[2] = ra2; sa[3] = ra3;
        sbp[0] = rb0; sbp[1] = rb1; sbp[2] = rb2; sbp[3] = rb3;
        __syncthreads();
        #pragma unroll
        for (int kk = 0; kk < 4; kk++) {
            uint af[4][4], bf[2][4];
            #pragma unroll
            for (int i = 0; i < 4; i++)
                ldm4(af[i][0], af[i][1], af[i][2], af[i][3],
                     abase + (uint)(i * 16 * SST * 2 + kk * 32));
            #pragma unroll
            for (int j2 = 0; j2 < 2; j2++)
                ldm4(bf[j2][0], bf[j2][1], bf[j2][2], bf[j2][3],
                     bbase + (uint)(j2 * 16 * SST * 2 + kk * 32));
            #pragma unroll
            for (int i = 0; i < 4; i++)
                #pragma unroll
                for (int j = 0; j < 4; j++)
                    mma16816(c[i][j], af[i], bf[j >> 1][(j & 1) * 2], bf[j >> 1][(j & 1) * 2 + 1]);
        }
    }

    int qr = lane >> 2, qc = (lane & 3) * 2;

    if (role == 0) {
        // plain stores into this CTA's private slab region
        #pragma unroll
        for (int i = 0; i < 4; i++) {
            #pragma unroll
            for (int h = 0; h < 2; h++) {
                int row_in = wm * 64 + i * 16 + h * 8 + qr;
                float* crow = cslab + (size_t)(u0 + row_in) * ldC + v0;
                #pragma unroll
                for (int j = 0; j < 4; j++) {
                    int col_in = wn * 32 + j * 8 + qc;
                    *(float2*)&crow[col_in] = make_float2(c[i][j][h * 2], c[i][j][h * 2 + 1]);
                }
            }
        }
    } else {
        float* cd = (float*)smA;
        float* cp = cd + 128;
        float* cc = cd + 256;
        __syncthreads();
        if (tid < 128) { cd[tid] = 0.f; cp[tid] = 0.f; cc[tid] = 0.f; }
        __syncthreads();
        #pragma unroll
        for (int i = 0; i < 4; i++) {
            #pragma unroll
            for (int h = 0; h < 2; h++) {
                int row_in = wm * 64 + i * 16 + h * 8 + qr;
                int gi = i0 + row_in;
                const int* mrow = mask + (size_t)gi * B + j0;
                float rowD = 0.f, rowP = 0.f, rowC = 0.f;
                #pragma unroll
                for (int j = 0; j < 4; j++) {
                    int col_in = wn * 32 + j * 8 + qc;
                    int2 mv = __ldcs((const int2*)(mrow + col_in));
                    float s0 = c[i][j][h * 2]     * 5.0f;
                    float s1 = c[i][j][h * 2 + 1] * 5.0f;
                    float e0 = __expf(s0), e1 = __expf(s1);
                    if (gi == j0 + col_in)     e0 = 0.f;   // diag excluded from denom
                    if (gi == j0 + col_in + 1) e1 = 0.f;
                    rowD += e0 + e1;
                    if (mv.x) { rowP += s0; rowC += 1.f; }
                    if (mv.y) { rowP += s1; rowC += 1.f; }
                }
                // reduce across the 4 lanes holding this row (lane bits 0-1)
                #pragma unroll
                for (int o = 1; o < 4; o <<= 1) {
                    rowD += __shfl_xor_sync(0xffffffffu, rowD, o);
                    rowP += __shfl_xor_sync(0xffffffffu, rowP, o);
                    rowC += __shfl_xor_sync(0xffffffffu, rowC, o);
                }
                if ((lane & 3) == 0) {
                    atomicAdd(&cd[row_in], rowD);
                    if (rowC != 0.f) {
                        atomicAdd(&cp[row_in], rowP);
                        atomicAdd(&cc[row_in], rowC);
                    }
                }
            }
        }
        __syncthreads();
        if (tid < 128) {
            atomicAdd(&g_denom[i0 + tid], cd[tid]);
            float cnt = cc[tid];
            if (cnt != 0.f) {
                atomicAdd(&g_possum[i0 + tid], cp[tid]);
                atomicAdd(&g_cnt[i0 + tid], cnt);
            }
        }
    }
}

// ---------------- weighted squared-Frobenius over g_C4 slabs ----------------
__global__ void square_kernel() {
    int i = blockIdx.x * blockDim.x + threadIdx.x;
    float vTT = 0.f, vTH = 0.f, vHH = 0.f;
    if (i < C_TT_SZ) {
        int u = i / 768, v = i - u * 768;
        int tu = u >> 7, tv = v >> 7;
        if (tv >= tu) {
            float c = g_C4[i] + g_C4[C_TOTAL + i] + g_C4[2 * C_TOTAL + i] + g_C4[3 * C_TOTAL + i];
            vTT = ((tv > tu) ? 2.f : 1.f) * c * c;
        }
    } else if (i < C_HH_OFF) {
        float c = g_C4[i] + g_C4[C_TOTAL + i] + g_C4[2 * C_TOTAL + i] + g_C4[3 * C_TOTAL + i];
        vTH = c * c;
    } else if (i < C_TOTAL) {
        float c = g_C4[i] + g_C4[C_TOTAL + i] + g_C4[2 * C_TOTAL + i] + g_C4[3 * C_TOTAL + i];
        vHH = c * c;
    }
    #pragma unroll
    for (int o = 16; o; o >>= 1) {
        vTT += __shfl_xor_sync(0xffffffffu, vTT, o);
        vTH += __shfl_xor_sync(0xffffffffu, vTH, o);
        vHH += __shfl_xor_sync(0xffffffffu, vHH, o);
    }
    __shared__ float sh[3][8];
    int lane = threadIdx.x & 31, wid = threadIdx.x >> 5;
    if (!lane) { sh[0][wid] = vTT; sh[1][wid] = vTH; sh[2][wid] = vHH; }
    __syncthreads();
    if (threadIdx.x < 3) {
        float s = 0.f;
        #pragma unroll
        for (int w = 0; w < 8; w++) s += sh[threadIdx.x][w];
        if (s != 0.f) atomicAdd(&g_scal[2 + threadIdx.x], s);
    }
}

// ---------------- finalize ----------------
__global__ void finalize_kernel(float* __restrict__ out) {
    int tid = threadIdx.x;
    float local = 0.f, np = 0.f;
    for (int r = tid; r < B; r += 256) {
        float c = g_cnt[r];
        if (c > 0.f) {
            local += logf(g_denom[r]) - g_possum[r] / c;
            np += 1.f;
        }
    }
    float qs = (tid < 128) ? g_qpart[tid] : 0.f;
    __shared__ float s1[256], s2[256], s3[256];
    s1[tid] = local; s2[tid] = np; s3[tid] = qs;
    __syncthreads();
    for (int s = 128; s; s >>= 1) {
        if (tid < s) { s1[tid] += s1[tid + s]; s2[tid] += s2[tid + s]; s3[tid] += s3[tid + s]; }
        __syncthreads();
    }
    if (!tid) {
        float cont = s1[0] / fmaxf(s2[0], 1.0f);
        float distill_sum = g_scal[4] * (1.0f / 16384.0f)
                          - g_scal[3] * (1.0f / 64.0f)
                          + g_scal[2];
        float distill = distill_sum / ((float)B * (float)B);
        float quant = s3[0] / ((float)B * (float)DL);
        out[0] = cont + 0.5f * distill + 0.01f * quant;
    }
}

// ---------------- entry point ----------------
extern "C" void kernel_launch(void* const* d_in, const int* in_sizes, int n_in,
                              void* d_out, int out_size) {
    const float* logits  = (const float*)d_in[0];
    const float* hash    = (const float*)d_in[1];
    const float* teacher = (const float*)d_in[2];
    const int*   mask    = (const int*)d_in[3];   // bool stored 4-byte; nonzero test
    float* out = (float*)d_out;

    prep_lh<<<128, 256>>>(logits, hash);
    prep_teacher<<<128, 256>>>(teacher);
    mega_kernel<<<NB_GRAM + NB_PAIR, 256>>>(mask);
    square_kernel<<<(C_TOTAL + 255) / 256, 256>>>();
    finalize_kernel<<<1, 256>>>(out);
}

// round 9
// speedup vs baseline: 11.5020x; 1.1555x over previous
#include <cuda_runtime.h>
#include <cuda_bf16.h>

#define B   4096
#define DL  128
#define DT  768

#define C_TT_SZ  (768*768)
#define C_TH_SZ  (768*128)
#define C_HH_SZ  (128*128)
#define C_TH_OFF (C_TT_SZ)
#define C_HH_OFF (C_TT_SZ + C_TH_SZ)
#define C_TOTAL  (C_TT_SZ + C_TH_SZ + C_HH_SZ)   // 704512

#define NB_GRAM 112     // TT 21*4 + TH 6*4 + HH 1*4 (split-K over batch)
#define NB_PAIR 1024
#define KC 64
#define SST 72          // smem row stride in bf16 (144 B: ldmatrix conflict-free)

typedef unsigned int uint;

// ---------------- device scratch ----------------
__device__ __nv_bfloat16 g_lnb[B * DL];      // normalized logits bf16, row-major [batch][feat]
__device__ __nv_bfloat16 g_tnT[DT * B];      // normalized teacher bf16, [feat][batch]
__device__ __nv_bfloat16 g_hT[DL * B];       // hash bf16, [feat][batch]
__device__ float g_C4[4 * C_TOTAL];          // split-K gram slabs (plain stores)
__device__ float g_denom[B];
__device__ float g_possum[B];
__device__ float g_cnt[B];
__device__ float g_scal[8];                  // [2]=G_TT [3]=G_TH [4]=G_HH
__device__ float g_qpart[128];

// ---------------- helpers ----------------
__device__ __forceinline__ uint smem_u32(const void* p) {
    uint a;
    asm("{ .reg .u64 t; cvta.to.shared.u64 t, %1; cvt.u32.u64 %0, t; }" : "=r"(a) : "l"(p));
    return a;
}
__device__ __forceinline__ void ldm4(uint& r0, uint& r1, uint& r2, uint& r3, uint addr) {
    asm volatile("ldmatrix.sync.aligned.m8n8.x4.shared.b16 {%0,%1,%2,%3}, [%4];"
                 : "=r"(r0), "=r"(r1), "=r"(r2), "=r"(r3) : "r"(addr));
}
__device__ __forceinline__ void mma16816(float* c, const uint* a, uint b0, uint b1) {
    asm volatile("mma.sync.aligned.m16n8k16.row.col.f32.bf16.bf16.f32 "
        "{%0,%1,%2,%3}, {%4,%5,%6,%7}, {%8,%9}, {%0,%1,%2,%3};"
        : "+f"(c[0]), "+f"(c[1]), "+f"(c[2]), "+f"(c[3])
        : "r"(a[0]), "r"(a[1]), "r"(a[2]), "r"(a[3]), "r"(b0), "r"(b1));
}
__device__ __forceinline__ uint bf2(float lo, float hi) {
    __nv_bfloat162 p = __floats2bfloat162_rn(lo, hi);
    return *(uint*)&p;
}

// ---------------- prep: logits normalize->bf16 rows, hash transpose->bf16, quant ----
__global__ void __launch_bounds__(256) prep_lh(const float* __restrict__ logits,
                                               const float* __restrict__ hash) {
    __shared__ float S[32][129];
    __shared__ float H[32][129];
    __shared__ float rinv[32];
    __shared__ float qsh[8];
    int blk = blockIdx.x, tid = threadIdx.x;
    int lane = tid & 31, w = tid >> 5;
    int r0 = blk * 32;

    float q = 0.f;
    #pragma unroll
    for (int it = 0; it < 16; it++) {
        int idx = tid + it * 256;
        int row = idx >> 7, f = idx & 127;
        float x = logits[(size_t)(r0 + row) * DL + f];
        S[row][f] = x;
        q += fabsf(fabsf(x) - 1.0f);
        H[row][f] = hash[(size_t)(r0 + row) * DL + f];
    }
    if (tid < 32) {
        int i = r0 + tid;
        g_denom[i] = 0.f; g_possum[i] = 0.f; g_cnt[i] = 0.f;
    }
    if (blk == 0 && tid < 8) g_scal[tid] = 0.f;
    __syncthreads();

    #pragma unroll
    for (int rr = 0; rr < 4; rr++) {
        int r = w * 4 + rr;
        float v0 = S[r][lane], v1 = S[r][lane + 32], v2 = S[r][lane + 64], v3 = S[r][lane + 96];
        float ss = v0 * v0 + v1 * v1 + v2 * v2 + v3 * v3;
        #pragma unroll
        for (int o = 16; o; o >>= 1) ss += __shfl_xor_sync(0xffffffffu, ss, o);
        if (!lane) rinv[r] = 1.0f / fmaxf(sqrtf(ss), 1e-12f);
    }
    __syncthreads();

    {   // normalized bf16 rows: 8 threads per row, 16 feats per thread
        int row = tid >> 3, f0 = (tid & 7) * 16;
        float riv = rinv[row];
        uint out[8];
        #pragma unroll
        for (int c = 0; c < 8; c++)
            out[c] = bf2(S[row][f0 + 2 * c] * riv, S[row][f0 + 2 * c + 1] * riv);
        uint4* dst = (uint4*)(g_lnb + (size_t)(r0 + row) * DL + f0);
        dst[0] = make_uint4(out[0], out[1], out[2], out[3]);
        dst[1] = make_uint4(out[4], out[5], out[6], out[7]);
    }

    {   // hash transpose bf16: thread -> (feature, 16-batch half)
        int f = tid & 127, h = tid >> 7;
        uint out[8];
        #pragma unroll
        for (int i = 0; i < 8; i++)
            out[i] = bf2(H[h * 16 + 2 * i][f], H[h * 16 + 2 * i + 1][f]);
        uint4* dst = (uint4*)(g_hT + (size_t)f * B + r0 + h * 16);
        dst[0] = make_uint4(out[0], out[1], out[2], out[3]);
        dst[1] = make_uint4(out[4], out[5], out[6], out[7]);
    }

    #pragma unroll
    for (int o = 16; o; o >>= 1) q += __shfl_xor_sync(0xffffffffu, q, o);
    if (!lane) qsh[w] = q;
    __syncthreads();
    if (!tid) {
        float s = 0.f;
        #pragma unroll
        for (int i = 0; i < 8; i++) s += qsh[i];
        g_qpart[blk] = s;
    }
}

// ---------------- prep: teacher normalize -> bf16 transposed [feat][batch] ----
__global__ void __launch_bounds__(256) prep_teacher(const float* __restrict__ t) {
    __shared__ float S[32][129];
    __shared__ float rinv[32];
    int blk = blockIdx.x, tid = threadIdx.x;
    int lane = tid & 31, w = tid >> 5;
    int r0 = blk * 32;

    #pragma unroll
    for (int rr = 0; rr < 4; rr++) {
        int r = w * 4 + rr;
        const float* p = t + (size_t)(r0 + r) * DT;
        float ss = 0.f;
        #pragma unroll
        for (int u = 0; u < 24; u++) { float x = p[lane + u * 32]; ss += x * x; }
        #pragma unroll
        for (int o = 16; o; o >>= 1) ss += __shfl_xor_sync(0xffffffffu, ss, o);
        if (!lane) rinv[r] = 1.0f / fmaxf(sqrtf(ss), 1e-12f);
    }
    __syncthreads();

    for (int chunk = 0; chunk < 6; chunk++) {
        int f0 = chunk * 128;
        #pragma unroll
        for (int it = 0; it < 16; it++) {
            int idx = tid + it * 256;
            int row = idx >> 7, f = idx & 127;
            S[row][f] = t[(size_t)(r0 + row) * DT + f0 + f];
        }
        __syncthreads();
        int f = tid & 127, h = tid >> 7;
        uint out[8];
        #pragma unroll
        for (int i = 0; i < 8; i++) {
            int ra = h * 16 + 2 * i, rb = ra + 1;
            out[i] = bf2(S[ra][f] * rinv[ra], S[rb][f] * rinv[rb]);
        }
        uint4* dst = (uint4*)(g_tnT + (size_t)(f0 + f) * B + r0 + h * 16);
        dst[0] = make_uint4(out[0], out[1], out[2], out[3]);
        dst[1] = make_uint4(out[4], out[5], out[6], out[7]);
        __syncthreads();
    }
}

// ---------------- mega: all Grams via mma.sync bf16 ----------------
__global__ void __launch_bounds__(256) mega_kernel(const int* __restrict__ mask) {
    __shared__ __align__(16) __nv_bfloat16 smA[128 * SST];   // 18432 B
    __shared__ __align__(16) __nv_bfloat16 smB[128 * SST];   // 18432 B
    __shared__ uint bmap[128][4];                            // 2 KB positive-mask bitmap

    int tid = threadIdx.x, lane = tid & 31, wid = tid >> 5;
    int wm = wid & 1, wn = wid >> 1;       // warp tile (64 x 32) at (wm*64, wn*32)
    int b = blockIdx.x;

    const __nv_bfloat16 *srcA, *srcB;
    size_t ldA, ldB;
    int nchunk, role;
    int u0 = 0, v0 = 0, ldC = 0;
    float* cslab = 0;
    int i0 = 0, j0 = 0;

    if (b < NB_GRAM) {
        role = 0;
        int kchunk;
        if (b < 84) {                       // TT upper triangle (21 tiles x 4 k-chunks)
            int tt = b >> 2; kchunk = b & 3;
            int tu = 0;
            while (tt >= 6 - tu) { tt -= 6 - tu; tu++; }
            int tv = tu + tt;
            u0 = tu * 128; v0 = tv * 128;
            srcA = g_tnT + (size_t)u0 * B; srcB = g_tnT + (size_t)v0 * B;
            cslab = g_C4 + (size_t)kchunk * C_TOTAL; ldC = 768;
        } else if (b < 108) {               // TH (6 tiles x 4)
            int r = b - 84; int tt = r >> 2; kchunk = r & 3;
            u0 = tt * 128; v0 = 0;
            srcA = g_tnT + (size_t)u0 * B; srcB = g_hT;
            cslab = g_C4 + (size_t)kchunk * C_TOTAL + C_TH_OFF; ldC = 128;
        } else {                            // HH (1 tile x 4)
            kchunk = b - 108;
            srcA = g_hT; srcB = g_hT;
            cslab = g_C4 + (size_t)kchunk * C_TOTAL + C_HH_OFF; ldC = 128;
        }
        srcA += (size_t)kchunk * 1024;
        srcB += (size_t)kchunk * 1024;
        ldA = B; ldB = B;
        nchunk = 1024 / KC;                 // 16
    } else {
        role = 1;
        int idx = b - NB_GRAM;
        i0 = (idx >> 5) * 128; j0 = (idx & 31) * 128;
        srcA = g_lnb + (size_t)i0 * DL;
        srcB = g_lnb + (size_t)j0 * DL;
        ldA = DL; ldB = DL;
        nchunk = DL / KC;                   // 2

        // ---- cooperative mask -> bitmap: warp w owns rows {w, w+8, ...} ----
        #pragma unroll
        for (int rr = 0; rr < 16; rr += 2) {
            int ra = wid + (rr << 3);
            int rb = ra + 8;
            const int* pa = mask + (size_t)(i0 + ra) * B + j0 + lane;
            const int* pb = mask + (size_t)(i0 + rb) * B + j0 + lane;
            int va0 = __ldcs(pa), va1 = __ldcs(pa + 32), va2 = __ldcs(pa + 64), va3 = __ldcs(pa + 96);
            int vb0 = __ldcs(pb), vb1 = __ldcs(pb + 32), vb2 = __ldcs(pb + 64), vb3 = __ldcs(pb + 96);
            uint ba0 = __ballot_sync(0xffffffffu, va0 != 0);
            uint ba1 = __ballot_sync(0xffffffffu, va1 != 0);
            uint ba2 = __ballot_sync(0xffffffffu, va2 != 0);
            uint ba3 = __ballot_sync(0xffffffffu, va3 != 0);
            uint bb0 = __ballot_sync(0xffffffffu, vb0 != 0);
            uint bb1 = __ballot_sync(0xffffffffu, vb1 != 0);
            uint bb2 = __ballot_sync(0xffffffffu, vb2 != 0);
            uint bb3 = __ballot_sync(0xffffffffu, vb3 != 0);
            if (!lane) {
                bmap[ra][0] = ba0; bmap[ra][1] = ba1; bmap[ra][2] = ba2; bmap[ra][3] = ba3;
                bmap[rb][0] = bb0; bmap[rb][1] = bb1; bmap[rb][2] = bb2; bmap[rb][3] = bb3;
            }
        }
    }

    float c[4][4][4];
    #pragma unroll
    for (int i = 0; i < 4; i++)
        #pragma unroll
        for (int j = 0; j < 4; j++)
            #pragma unroll
            for (int e = 0; e < 4; e++) c[i][j][e] = 0.f;

    uint smA32 = smem_u32(smA), smB32 = smem_u32(smB);
    int g = lane >> 3, lr = lane & 7;
    // A frag addresses (row-major m16k16): matrices [m0-7,k0][m8-15,k0][m0-7,k8][m8-15,k8]
    uint abase = smA32 + (uint)(((wm * 64 + ((g & 1) << 3) + lr) * SST + ((g >> 1) << 3)) * 2);
    // B frag addresses: matrices [n0-7,k0][n0-7,k8][n8-15,k0][n8-15,k8]
    uint bbase = smB32 + (uint)(((wn * 32 + ((g >> 1) << 3) + lr) * SST + ((g & 1) << 3)) * 2);

    int lrow = tid >> 1, lh = (tid & 1) * 32;   // loader: row, 32-bf16 half
    const __nv_bfloat16* pa = srcA + (size_t)lrow * ldA + lh;
    const __nv_bfloat16* pb = srcB + (size_t)lrow * ldB + lh;
    uint4* sa  = (uint4*)(smA + lrow * SST + lh);
    uint4* sbp = (uint4*)(smB + lrow * SST + lh);

    for (int cch = 0; cch < nchunk; cch++) {
        const uint4* ga = (const uint4*)(pa + cch * KC);
        const uint4* gb = (const uint4*)(pb + cch * KC);
        uint4 ra0 = ga[0], ra1 = ga[1], ra2 = ga[2], ra3 = ga[3];
        uint4 rb0 = gb[0], rb1 = gb[1], rb2 = gb[2], rb3 = gb[3];
        __syncthreads();
        sa[0] = ra0; sa[1] = ra1; sa[2] = ra2; sa[3] = ra3;
        sbp[0] = rb0; sbp[1] = rb1; sbp[2] = rb2; sbp[3] = rb3;
        __syncthreads();
        #pragma unroll
        for (int kk = 0; kk < 4; kk++) {
            uint af[4][4], bf[2][4];
            #pragma unroll
            for (int i = 0; i < 4; i++)
                ldm4(af[i][0], af[i][1], af[i][2], af[i][3],
                     abase + (uint)(i * 16 * SST * 2 + kk * 32));
            #pragma unroll
            for (int j2 = 0; j2 < 2; j2++)
                ldm4(bf[j2][0], bf[j2][1], bf[j2][2], bf[j2][3],
                     bbase + (uint)(j2 * 16 * SST * 2 + kk * 32));
            #pragma unroll
            for (int i = 0; i < 4; i++)
                #pragma unroll
                for (int j = 0; j < 4; j++)
                    mma16816(c[i][j], af[i], bf[j >> 1][(j & 1) * 2], bf[j >> 1][(j & 1) * 2 + 1]);
        }
    }

    int qr = lane >> 2, qc = (lane & 3) * 2;

    if (role == 0) {
        // plain stores into this CTA's private slab region
        #pragma unroll
        for (int i = 0; i < 4; i++) {
            #pragma unroll
            for (int h = 0; h < 2; h++) {
                int row_in = wm * 64 + i * 16 + h * 8 + qr;
                float* crow = cslab + (size_t)(u0 + row_in) * ldC + v0;
                #pragma unroll
                for (int j = 0; j < 4; j++) {
                    int col_in = wn * 32 + j * 8 + qc;
                    *(float2*)&crow[col_in] = make_float2(c[i][j][h * 2], c[i][j][h * 2 + 1]);
                }
            }
        }
    } else {
        float* cd = (float*)smA;
        float* cp = cd + 128;
        float* cc = cd + 256;
        __syncthreads();
        if (tid < 128) { cd[tid] = 0.f; cp[tid] = 0.f; cc[tid] = 0.f; }
        __syncthreads();
        #pragma unroll
        for (int i = 0; i < 4; i++) {
            #pragma unroll
            for (int h = 0; h < 2; h++) {
                int row_in = wm * 64 + i * 16 + h * 8 + qr;
                int gi = i0 + row_in;
                uint mw = bmap[row_in][wn];
                float rowD = 0.f, rowP = 0.f, rowC = 0.f;
                #pragma unroll
                for (int j = 0; j < 4; j++) {
                    int col_in = wn * 32 + j * 8 + qc;
                    float s0 = c[i][j][h * 2]     * 5.0f;
                    float s1 = c[i][j][h * 2 + 1] * 5.0f;
                    float e0 = __expf(s0), e1 = __expf(s1);
                    if (gi == j0 + col_in)     e0 = 0.f;   // diag excluded from denom
                    if (gi == j0 + col_in + 1) e1 = 0.f;
                    rowD += e0 + e1;
                    if ((mw >> (j * 8 + qc)) & 1u)       { rowP += s0; rowC += 1.f; }
                    if ((mw >> (j * 8 + qc + 1)) & 1u)   { rowP += s1; rowC += 1.f; }
                }
                // reduce across the 4 lanes holding this row (lane bits 0-1)
                #pragma unroll
                for (int o = 1; o < 4; o <<= 1) {
                    rowD += __shfl_xor_sync(0xffffffffu, rowD, o);
                    rowP += __shfl_xor_sync(0xffffffffu, rowP, o);
                    rowC += __shfl_xor_sync(0xffffffffu, rowC, o);
                }
                if ((lane & 3) == 0) {
                    atomicAdd(&cd[row_in], rowD);
                    if (rowC != 0.f) {
                        atomicAdd(&cp[row_in], rowP);
                        atomicAdd(&cc[row_in], rowC);
                    }
                }
            }
        }
        __syncthreads();
        if (tid < 128) {
            atomicAdd(&g_denom[i0 + tid], cd[tid]);
            float cnt = cc[tid];
            if (cnt != 0.f) {
                atomicAdd(&g_possum[i0 + tid], cp[tid]);
                atomicAdd(&g_cnt[i0 + tid], cnt);
            }
        }
    }
}

// ---------------- weighted squared-Frobenius over g_C4 slabs (float4) ----------------
__global__ void __launch_bounds__(256) square_kernel() {
    int t = blockIdx.x * blockDim.x + threadIdx.x;
    int base = t * 4;
    float vTT = 0.f, vTH = 0.f, vHH = 0.f;
    if (base < C_TOTAL) {
        float4 c0 = *(const float4*)(g_C4 + base);
        float4 c1 = *(const float4*)(g_C4 + C_TOTAL + base);
        float4 c2 = *(const float4*)(g_C4 + 2 * C_TOTAL + base);
        float4 c3 = *(const float4*)(g_C4 + 3 * C_TOTAL + base);
        float s0 = c0.x + c1.x + c2.x + c3.x;
        float s1 = c0.y + c1.y + c2.y + c3.y;
        float s2 = c0.z + c1.z + c2.z + c3.z;
        float s3 = c0.w + c1.w + c2.w + c3.w;
        float ssq = s0 * s0 + s1 * s1 + s2 * s2 + s3 * s3;
        if (base < C_TT_SZ) {
            int u = base / 768, v = base - u * 768;   // float4 never straddles a row (768%4==0)
            int tu = u >> 7, tv = v >> 7;             // nor a 128-tile (128%4==0)
            vTT = (tv > tu) ? 2.f * ssq : ((tv == tu) ? ssq : 0.f);
        } else if (base < C_HH_OFF) {
            vTH = ssq;
        } else {
            vHH = ssq;
        }
    }
    #pragma unroll
    for (int o = 16; o; o >>= 1) {
        vTT += __shfl_xor_sync(0xffffffffu, vTT, o);
        vTH += __shfl_xor_sync(0xffffffffu, vTH, o);
        vHH += __shfl_xor_sync(0xffffffffu, vHH, o);
    }
    __shared__ float sh[3][8];
    int lane = threadIdx.x & 31, wid = threadIdx.x >> 5;
    if (!lane) { sh[0][wid] = vTT; sh[1][wid] = vTH; sh[2][wid] = vHH; }
    __syncthreads();
    if (threadIdx.x < 3) {
        float s = 0.f;
        #pragma unroll
        for (int w = 0; w < 8; w++) s += sh[threadIdx.x][w];
        if (s != 0.f) atomicAdd(&g_scal[2 + threadIdx.x], s);
    }
}

// ---------------- finalize ----------------
__global__ void finalize_kernel(float* __restrict__ out) {
    int tid = threadIdx.x;
    float local = 0.f, np = 0.f;
    for (int r = tid; r < B; r += 256) {
        float c = g_cnt[r];
        if (c > 0.f) {
            local += logf(g_denom[r]) - g_possum[r] / c;
            np += 1.f;
        }
    }
    float qs = (tid < 128) ? g_qpart[tid] : 0.f;
    __shared__ float s1[256], s2[256], s3[256];
    s1[tid] = local; s2[tid] = np; s3[tid] = qs;
    __syncthreads();
    for (int s = 128; s; s >>= 1) {
        if (tid < s) { s1[tid] += s1[tid + s]; s2[tid] += s2[tid + s]; s3[tid] += s3[tid + s]; }
        __syncthreads();
    }
    if (!tid) {
        float cont = s1[0] / fmaxf(s2[0], 1.0f);
        float distill_sum = g_scal[4] * (1.0f / 16384.0f)
                          - g_scal[3] * (1.0f / 64.0f)
                          + g_scal[2];
        float distill = distill_sum / ((float)B * (float)B);
        float quant = s3[0] / ((float)B * (float)DL);
        out[0] = cont + 0.5f * distill + 0.01f * quant;
    }
}

// ---------------- entry point ----------------
extern "C" void kernel_launch(void* const* d_in, const int* in_sizes, int n_in,
                              void* d_out, int out_size) {
    const float* logits  = (const float*)d_in[0];
    const float* hash    = (const float*)d_in[1];
    const float* teacher = (const float*)d_in[2];
    const int*   mask    = (const int*)d_in[3];   // bool stored 4-byte; nonzero test
    float* out = (float*)d_out;

    prep_lh<<<128, 256>>>(logits, hash);
    prep_teacher<<<128, 256>>>(teacher);
    mega_kernel<<<NB_GRAM + NB_PAIR, 256>>>(mask);
    square_kernel<<<(C_TOTAL / 4 + 255) / 256, 256>>>();
    finalize_kernel<<<1, 256>>>(out);
}